// round 11
// baseline (speedup 1.0000x reference)
#include <cuda_runtime.h>
#include <cuda_bf16.h>
#include <cstdint>

#define DIM     640
#define HEADS   10
#define HD      64
#define B_SZ    16
#define SEQ     1024
#define M_TOT   (B_SZ * SEQ)     // 16384
#define QKV_N   (3 * DIM)        // 1920
// q pre-scale: DIM^-0.5 * log2(e), folded into q at QKV epilogue
#define QSCALE  0.0570280394796554f

// ---------------- scratch (device globals) ----------------
__device__ __nv_bfloat16 g_xh[(size_t)M_TOT * DIM];
__device__ __nv_bfloat16 g_xl[(size_t)M_TOT * DIM];
__device__ __nv_bfloat16 g_wqh[(size_t)DIM * QKV_N];   // w_qkv hi  [640][1920] natural
__device__ __nv_bfloat16 g_wql[(size_t)DIM * QKV_N];
__device__ __nv_bfloat16 g_woh[(size_t)DIM * DIM];     // w_out hi  [640][640] natural
__device__ __nv_bfloat16 g_wol[(size_t)DIM * DIM];
// per-head q/k/v, bf16 hi/lo: [B*HEADS][SEQ][64]  (q pre-scaled by QSCALE)
__device__ __nv_bfloat16 g_qh[(size_t)B_SZ * HEADS * SEQ * HD];
__device__ __nv_bfloat16 g_ql[(size_t)B_SZ * HEADS * SEQ * HD];
__device__ __nv_bfloat16 g_kh[(size_t)B_SZ * HEADS * SEQ * HD];
__device__ __nv_bfloat16 g_kl[(size_t)B_SZ * HEADS * SEQ * HD];
__device__ __nv_bfloat16 g_vh[(size_t)B_SZ * HEADS * SEQ * HD];
__device__ __nv_bfloat16 g_vl[(size_t)B_SZ * HEADS * SEQ * HD];
__device__ __nv_bfloat16 g_ah[(size_t)M_TOT * DIM];    // attention out hi (bf16 split)
__device__ __nv_bfloat16 g_al[(size_t)M_TOT * DIM];

// ---------------- helpers ----------------
__device__ __forceinline__ uint32_t smem_u32(const void* p) {
    uint32_t a;
    asm("{ .reg .u64 t; cvta.to.shared.u64 t, %1; cvt.u32.u64 %0, t; }"
        : "=r"(a) : "l"(p));
    return a;
}
__device__ __forceinline__ void ldmatrix_x4(uint32_t* r, uint32_t addr) {
    asm volatile("ldmatrix.sync.aligned.m8n8.x4.shared.b16 {%0,%1,%2,%3}, [%4];"
                 : "=r"(r[0]), "=r"(r[1]), "=r"(r[2]), "=r"(r[3]) : "r"(addr));
}
__device__ __forceinline__ void ldmatrix_x4_trans(uint32_t* r, uint32_t addr) {
    asm volatile("ldmatrix.sync.aligned.m8n8.x4.trans.shared.b16 {%0,%1,%2,%3}, [%4];"
                 : "=r"(r[0]), "=r"(r[1]), "=r"(r[2]), "=r"(r[3]) : "r"(addr));
}
__device__ __forceinline__ void mma_bf16(float* c, const uint32_t* a, const uint32_t* b) {
    asm volatile("mma.sync.aligned.m16n8k16.row.col.f32.bf16.bf16.f32 "
                 "{%0,%1,%2,%3}, {%4,%5,%6,%7}, {%8,%9}, {%0,%1,%2,%3};"
                 : "+f"(c[0]), "+f"(c[1]), "+f"(c[2]), "+f"(c[3])
                 : "r"(a[0]), "r"(a[1]), "r"(a[2]), "r"(a[3]), "r"(b[0]), "r"(b[1]));
}
__device__ __forceinline__ float ex2(float x) {
    float r;
    asm("ex2.approx.ftz.f32 %0, %1;" : "=f"(r) : "f"(x));
    return r;
}
__device__ __forceinline__ void split2(float x, float y, uint32_t& hi, uint32_t& lo) {
    __nv_bfloat162 h;
    h.x = __float2bfloat16(x);
    h.y = __float2bfloat16(y);
    __nv_bfloat162 l;
    l.x = __float2bfloat16(x - __bfloat162float(h.x));
    l.y = __float2bfloat16(y - __bfloat162float(h.y));
    hi = *(uint32_t*)&h;
    lo = *(uint32_t*)&l;
}

#define CPASYNC(dst, src) \
    asm volatile("cp.async.cg.shared.global [%0], [%1], 16;" \
                 :: "r"(dst), "l"(src) : "memory")
#define CPCOMMIT() asm volatile("cp.async.commit_group;" ::: "memory")
#define CPWAIT1()  asm volatile("cp.async.wait_group 1;" ::: "memory")
#define CPWAIT0()  asm volatile("cp.async.wait_group 0;" ::: "memory")

// 64B-row tile (32 bf16), chunk^((row>>1)&3) swizzle — GEMM A tiles (BK=32)
__device__ __forceinline__ uint32_t tile_off(int row, int chunk) {
    return (uint32_t)(row * 64 + 16 * (chunk ^ ((row >> 1) & 3)));
}
// 256B-row tile (128 bf16), chunk^(row&7) swizzle — GEMM B tiles [32k][128n]
__device__ __forceinline__ uint32_t boff(int row, int chunk) {
    return (uint32_t)(row * 256 + 16 * (chunk ^ (row & 7)));
}
// 128B-row tile (64 bf16), chunk^(row&7) swizzle — flash Q/K/V tiles
__device__ __forceinline__ uint32_t foff(int row, int chunk) {
    return (uint32_t)(row * 128 + 16 * (chunk ^ (row & 7)));
}

// ---------------- merged split kernel (float4-vectorized, 1 launch) ----------------
#define NX  (M_TOT * DIM)          // 10485760
#define NWQ (DIM * QKV_N)          // 1228800
#define NWO (DIM * DIM)            // 409600
#define NSPLIT4 ((NX + NWQ + NWO) / 4)

__global__ void split_all(const float* __restrict__ x,
                          const float* __restrict__ wq,
                          const float* __restrict__ wo)
{
    const int i4 = blockIdx.x * 256 + threadIdx.x;
    if (i4 >= NSPLIT4) return;
    const float* src;
    __nv_bfloat16 *hi, *lo;
    int idx = i4 * 4;
    if (idx < NX)            { src = x;  hi = g_xh;  lo = g_xl; }
    else if (idx < NX + NWQ) { idx -= NX;  src = wq; hi = g_wqh; lo = g_wql; }
    else                     { idx -= NX + NWQ; src = wo; hi = g_woh; lo = g_wol; }

    float4 v = *(const float4*)(src + idx);
    uint32_t h0, l0, h1, l1;
    split2(v.x, v.y, h0, l0);
    split2(v.z, v.w, h1, l1);
    uint2 hh; hh.x = h0; hh.y = h1;
    uint2 ll; ll.x = l0; ll.y = l1;
    *(uint2*)(hi + idx) = hh;
    *(uint2*)(lo + idx) = ll;
}

// ---------------- mma.sync split-bf16 GEMM (cp.async 3-stage) ----------------
// C[M,N] = A[M,K] @ W[K,N] + bias. CTA tile MT x 128, BK=32, 8 warps.
// MT=128: warp 64x32 (mi=4). MT=64: warp 32x32 (mi=2) — finer grid for tails.
#define GS_STAGE 32768
#define GS_AL    8192
#define GS_BH    16384
#define GS_BL    24576
#define GEMM_SMEM (3 * GS_STAGE)

template <bool QKV, int MT>
__global__ __launch_bounds__(256, 2)
void gemm_mma(const __nv_bfloat16* __restrict__ Ah, const __nv_bfloat16* __restrict__ Al,
              const __nv_bfloat16* __restrict__ Bh, const __nv_bfloat16* __restrict__ Bl,
              const float* __restrict__ bias, float* __restrict__ Cout,
              int Ntot, int Ktot)
{
    extern __shared__ char gs[];
    const uint32_t sb = smem_u32(gs);

    constexpr int MI = MT / 32;          // m-frags per warp
    const int tid  = threadIdx.x;
    const int lane = tid & 31;
    const int wid  = tid >> 5;
    const int wm   = wid >> 2;
    const int wn   = wid & 3;
    const int m0   = blockIdx.y * MT;
    const int n0   = blockIdx.x * 128;

    float c[MI][4][4];
    #pragma unroll
    for (int i = 0; i < MI; ++i)
        #pragma unroll
        for (int j = 0; j < 4; ++j)
            #pragma unroll
            for (int t = 0; t < 4; ++t) c[i][j][t] = 0.f;

    auto load_stage = [&](int stage, int k0) {
        const uint32_t s0 = sb + stage * GS_STAGE;
        #pragma unroll
        for (int it = 0; it < MT / 64; ++it) {
            const int idx = it * 256 + tid;
            const int row = idx >> 2;
            const int cc  = idx & 3;
            const uint32_t so = tile_off(row, cc);
            const size_t ga = (size_t)(m0 + row) * Ktot + k0 + cc * 8;
            CPASYNC(s0 + so,         Ah + ga);
            CPASYNC(s0 + GS_AL + so, Al + ga);
        }
        #pragma unroll
        for (int it = 0; it < 2; ++it) {
            const int idx = it * 256 + tid;
            const int row = idx >> 4;
            const int cc  = idx & 15;
            const uint32_t so = boff(row, cc);
            const size_t gb = (size_t)(k0 + row) * Ntot + n0 + cc * 8;
            CPASYNC(s0 + GS_BH + so, Bh + gb);
            CPASYNC(s0 + GS_BL + so, Bl + gb);
        }
        CPCOMMIT();
    };

    const int nk = Ktot / 32;
    load_stage(0, 0);
    load_stage(1, 32);

    const int hilo_b = (lane >> 4) * (GS_BL - GS_BH);
    const int krow_b = lane & 15;

    int st = 0;
    for (int ki = 0; ki < nk; ++ki) {
        if (ki + 2 <= nk) { CPWAIT1(); } else { CPWAIT0(); }
        __syncthreads();
        if (ki + 2 < nk) {
            int st2 = st + 2; if (st2 >= 3) st2 -= 3;
            load_stage(st2, (ki + 2) * 32);
        }

        const uint32_t s0 = sb + st * GS_STAGE;
        #pragma unroll
        for (int ks = 0; ks < 2; ++ks) {
            uint32_t b4[4][4];
            #pragma unroll
            for (int ni = 0; ni < 4; ++ni) {
                const int chn = wn * 4 + ni;
                ldmatrix_x4_trans(b4[ni],
                    s0 + GS_BH + hilo_b + boff(ks * 16 + krow_b, chn));
            }
            #pragma unroll
            for (int mi = 0; mi < MI; ++mi) {
                uint32_t ah[4], al[4];
                const int r = wm * (MT / 2) + mi * 16 + (lane & 15);
                const uint32_t off = tile_off(r, ks * 2 + (lane >> 4));
                ldmatrix_x4(ah, s0 + off);
                ldmatrix_x4(al, s0 + GS_AL + off);
                #pragma unroll
                for (int ni = 0; ni < 4; ++ni) mma_bf16(c[mi][ni], ah, b4[ni] + 0);
                #pragma unroll
                for (int ni = 0; ni < 4; ++ni) mma_bf16(c[mi][ni], ah, b4[ni] + 2);
                #pragma unroll
                for (int ni = 0; ni < 4; ++ni) mma_bf16(c[mi][ni], al, b4[ni] + 0);
            }
        }
        if (++st >= 3) st = 0;
    }

    #pragma unroll
    for (int mi = 0; mi < MI; ++mi) {
        #pragma unroll
        for (int ni = 0; ni < 4; ++ni) {
            const int r0  = m0 + wm * (MT / 2) + mi * 16 + (lane >> 2);
            const int col = n0 + wn * 32 + ni * 8 + (lane & 3) * 2;
            const float b0 = bias[col], b1 = bias[col + 1];
            #pragma unroll
            for (int half = 0; half < 2; ++half) {
                const int r = r0 + half * 8;
                float vx = c[mi][ni][half * 2 + 0] + b0;
                float vy = c[mi][ni][half * 2 + 1] + b1;
                if (QKV) {
                    const int bb  = r >> 10;
                    const int iq  = r & 1023;
                    const int sel = col / DIM;
                    const int nc  = col - sel * DIM;
                    const int h   = nc >> 6;
                    const int d   = nc & 63;
                    if (sel == 0) { vx *= QSCALE; vy *= QSCALE; }
                    __nv_bfloat16* dh = (sel == 0) ? g_qh : (sel == 1) ? g_kh : g_vh;
                    __nv_bfloat16* dl = (sel == 0) ? g_ql : (sel == 1) ? g_kl : g_vl;
                    const size_t idx = (((size_t)(bb * HEADS + h)) * SEQ + iq) * HD + d;
                    uint32_t hi, lo;
                    split2(vx, vy, hi, lo);
                    *(uint32_t*)(dh + idx) = hi;
                    *(uint32_t*)(dl + idx) = lo;
                } else {
                    float2 v; v.x = vx; v.y = vy;
                    *(float2*)&Cout[(size_t)r * Ntot + col] = v;
                }
            }
        }
    }
}

// ---------------- flash attention with mma.sync (cp.async 2-stage K/V) ----------------
#define FQH 0
#define FQL 16384
#define FKV 32768
#define FKV_STRIDE 32768
#define FKL_O 8192
#define FVH_O 16384
#define FVL_O 24576
#define FLASH_SMEM (32768 + 2 * FKV_STRIDE)   // 98304

__global__ __launch_bounds__(256, 2)
void flash_mma()
{
    extern __shared__ char fs[];
    const uint32_t sb = smem_u32(fs);
    const int tid  = threadIdx.x;
    const int lane = tid & 31;
    const int wid  = tid >> 5;
    const int bh   = blockIdx.y;
    const int q0   = blockIdx.x * 128;
    const size_t base = (size_t)bh * SEQ * HD;

    auto load_kv = [&](int stage, int kb) {
        const uint32_t s0 = sb + FKV + stage * FKV_STRIDE;
        #pragma unroll
        for (int i = 0; i < 2; ++i) {
            const int idx = i * 256 + tid;
            const int row = idx >> 3, ch = idx & 7;
            const uint32_t so = foff(row, ch);
            const size_t g = base + (size_t)(kb + row) * HD + ch * 8;
            CPASYNC(s0 + so,         g_kh + g);
            CPASYNC(s0 + FKL_O + so, g_kl + g);
            CPASYNC(s0 + FVH_O + so, g_vh + g);
            CPASYNC(s0 + FVL_O + so, g_vl + g);
        }
        CPCOMMIT();
    };

    load_kv(0, 0);
    #pragma unroll
    for (int i = 0; i < 4; ++i) {
        const int idx = i * 256 + tid;
        const int row = idx >> 3, ch = idx & 7;
        const uint32_t so = foff(row, ch);
        const size_t g = base + (size_t)(q0 + row) * HD + ch * 8;
        *(uint4*)(fs + FQH + so) = *(const uint4*)(g_qh + g);
        *(uint4*)(fs + FQL + so) = *(const uint4*)(g_ql + g);
    }

    float O[8][4];
    #pragma unroll
    for (int i = 0; i < 8; ++i)
        #pragma unroll
        for (int t = 0; t < 4; ++t) O[i][t] = 0.f;
    float m0 = -1e30f, m1 = -1e30f, l0 = 0.f, l1 = 0.f;

    const int hilo_k = (lane >> 4) * FKL_O;
    const int hilo_v = (lane >> 4) * (FVL_O - FVH_O);

    const int nkb = SEQ / 64;
    for (int kbi = 0; kbi < nkb; ++kbi) {
        CPWAIT0();
        __syncthreads();
        if (kbi + 1 < nkb) load_kv((kbi + 1) & 1, (kbi + 1) * 64);

        const uint32_t s0 = sb + FKV + (kbi & 1) * FKV_STRIDE;

        float c[8][4];
        #pragma unroll
        for (int i = 0; i < 8; ++i)
            #pragma unroll
            for (int t = 0; t < 4; ++t) c[i][t] = 0.f;

        #pragma unroll
        for (int ks = 0; ks < 4; ++ks) {
            uint32_t qh[4], ql[4];
            {
                const int r  = wid * 16 + (lane & 15);
                const int ch = ks * 2 + (lane >> 4);
                ldmatrix_x4(qh, sb + FQH + foff(r, ch));
                ldmatrix_x4(ql, sb + FQL + foff(r, ch));
            }
            const int lr2 = lane & 7;
            const int lc2 = (lane >> 3) & 1;
            #pragma unroll
            for (int ng = 0; ng < 2; ++ng) {
                uint32_t kb4[4][4];
                #pragma unroll
                for (int j = 0; j < 4; ++j)
                    ldmatrix_x4(kb4[j],
                        s0 + hilo_k + foff((ng * 4 + j) * 8 + lr2, ks * 2 + lc2));
                #pragma unroll
                for (int j = 0; j < 4; ++j) mma_bf16(c[ng*4+j], qh, kb4[j] + 0);
                #pragma unroll
                for (int j = 0; j < 4; ++j) mma_bf16(c[ng*4+j], qh, kb4[j] + 2);
                #pragma unroll
                for (int j = 0; j < 4; ++j) mma_bf16(c[ng*4+j], ql, kb4[j] + 0);
            }
        }

        // online softmax (log2 domain)
        float rm0 = -1e30f, rm1 = -1e30f;
        #pragma unroll
        for (int ni = 0; ni < 8; ++ni) {
            rm0 = fmaxf(rm0, fmaxf(c[ni][0], c[ni][1]));
            rm1 = fmaxf(rm1, fmaxf(c[ni][2], c[ni][3]));
        }
        #pragma unroll
        for (int off = 1; off < 4; off <<= 1) {
            rm0 = fmaxf(rm0, __shfl_xor_sync(0xffffffffu, rm0, off));
            rm1 = fmaxf(rm1, __shfl_xor_sync(0xffffffffu, rm1, off));
        }
        const float mn0 = fmaxf(m0, rm0), mn1 = fmaxf(m1, rm1);
        if (!__all_sync(0xffffffffu, (mn0 == m0) && (mn1 == m1))) {
            const float cor0 = ex2(m0 - mn0), cor1 = ex2(m1 - mn1);
            l0 *= cor0; l1 *= cor1;
            #pragma unroll
            for (int nd = 0; nd < 8; ++nd) {
                O[nd][0] *= cor0; O[nd][1] *= cor0;
                O[nd][2] *= cor1; O[nd][3] *= cor1;
            }
            m0 = mn0; m1 = mn1;
        }

        float rs0 = 0.f, rs1 = 0.f;
        #pragma unroll
        for (int ni = 0; ni < 8; ++ni) {
            c[ni][0] = ex2(c[ni][0] - m0);
            c[ni][1] = ex2(c[ni][1] - m0);
            c[ni][2] = ex2(c[ni][2] - m1);
            c[ni][3] = ex2(c[ni][3] - m1);
            rs0 += c[ni][0] + c[ni][1];
            rs1 += c[ni][2] + c[ni][3];
        }
        #pragma unroll
        for (int off = 1; off < 4; off <<= 1) {
            rs0 += __shfl_xor_sync(0xffffffffu, rs0, off);
            rs1 += __shfl_xor_sync(0xffffffffu, rs1, off);
        }
        l0 += rs0;
        l1 += rs1;

        // O += P V
        #pragma unroll
        for (int ks2 = 0; ks2 < 4; ++ks2) {
            uint32_t ph[4], pl[4];
            split2(c[2*ks2][0],   c[2*ks2][1],   ph[0], pl[0]);
            split2(c[2*ks2][2],   c[2*ks2][3],   ph[1], pl[1]);
            split2(c[2*ks2+1][0], c[2*ks2+1][1], ph[2], pl[2]);
            split2(c[2*ks2+1][2], c[2*ks2+1][3], ph[3], pl[3]);
            const int vr = ks2 * 16 + (lane & 15);
            #pragma unroll
            for (int ng = 0; ng < 2; ++ng) {
                uint32_t vb4[4][4];
                #pragma unroll
                for (int j = 0; j < 4; ++j)
                    ldmatrix_x4_trans(vb4[j], s0 + FVH_O + hilo_v + foff(vr, ng * 4 + j));
                #pragma unroll
                for (int j = 0; j < 4; ++j) mma_bf16(O[ng*4+j], ph, vb4[j] + 0);
                #pragma unroll
                for (int j = 0; j < 4; ++j) mma_bf16(O[ng*4+j], ph, vb4[j] + 2);
                #pragma unroll
                for (int j = 0; j < 4; ++j) mma_bf16(O[ng*4+j], pl, vb4[j] + 0);
            }
        }
    }

    // epilogue
    const float inv0 = 1.f / l0, inv1 = 1.f / l1;
    const int b = bh / HEADS;
    const int h = bh - b * HEADS;
    const int r0 = q0 + wid * 16 + (lane >> 2);
    #pragma unroll
    for (int nd = 0; nd < 8; ++nd) {
        const int col = h * HD + nd * 8 + (lane & 3) * 2;
        uint32_t hi, lo;
        split2(O[nd][0] * inv0, O[nd][1] * inv0, hi, lo);
        size_t idx = ((size_t)(b * SEQ + r0)) * DIM + col;
        *(uint32_t*)(g_ah + idx) = hi;
        *(uint32_t*)(g_al + idx) = lo;
        split2(O[nd][2] * inv1, O[nd][3] * inv1, hi, lo);
        idx = ((size_t)(b * SEQ + r0 + 8)) * DIM + col;
        *(uint32_t*)(g_ah + idx) = hi;
        *(uint32_t*)(g_al + idx) = lo;
    }
}

// ---------------- launch ----------------
extern "C" void kernel_launch(void* const* d_in, const int* in_sizes, int n_in,
                              void* d_out, int out_size)
{
    const float* x     = (const float*)d_in[0];
    const float* w_qkv = (const float*)d_in[1];
    const float* b_qkv = (const float*)d_in[2];
    const float* w_out = (const float*)d_in[3];
    const float* b_out = (const float*)d_in[4];
    float* out = (float*)d_out;

    __nv_bfloat16 *xh, *xl, *wqh, *wql, *woh, *wol, *ah, *al;
    cudaGetSymbolAddress((void**)&xh,  g_xh);
    cudaGetSymbolAddress((void**)&xl,  g_xl);
    cudaGetSymbolAddress((void**)&wqh, g_wqh);
    cudaGetSymbolAddress((void**)&wql, g_wql);
    cudaGetSymbolAddress((void**)&woh, g_woh);
    cudaGetSymbolAddress((void**)&wol, g_wol);
    cudaGetSymbolAddress((void**)&ah,  g_ah);
    cudaGetSymbolAddress((void**)&al,  g_al);

    cudaFuncSetAttribute((const void*)gemm_mma<true, 64>,
                         cudaFuncAttributeMaxDynamicSharedMemorySize, GEMM_SMEM);
    cudaFuncSetAttribute((const void*)gemm_mma<false, 64>,
                         cudaFuncAttributeMaxDynamicSharedMemorySize, GEMM_SMEM);
    cudaFuncSetAttribute(flash_mma, cudaFuncAttributeMaxDynamicSharedMemorySize, FLASH_SMEM);

    // 0) all fp32 -> bf16 hi/lo splits in one vectorized launch
    split_all<<<(NSPLIT4 + 255) / 256, 256>>>(x, w_qkv, w_out);

    // 1) QKV GEMM (64M tiles: finer grid, smaller wave tail) -> q/k/v hi/lo
    gemm_mma<true, 64><<<dim3(QKV_N / 128, M_TOT / 64), 256, GEMM_SMEM>>>(
        xh, xl, wqh, wql, b_qkv, nullptr, QKV_N, DIM);

    // 2) flash attention (HMMA, log2-domain softmax) -> g_ah/g_al
    flash_mma<<<dim3(SEQ / 128, B_SZ * HEADS), 256, FLASH_SMEM>>>();

    // 3) out projection (64M tiles) -> d_out
    gemm_mma<false, 64><<<dim3(DIM / 128, M_TOT / 64), 256, GEMM_SMEM>>>(
        ah, al, woh, wol, b_out, out, DIM, DIM);
}

// round 12
// speedup vs baseline: 1.0186x; 1.0186x over previous
#include <cuda_runtime.h>
#include <cuda_bf16.h>
#include <cstdint>

#define DIM     640
#define HEADS   10
#define HD      64
#define B_SZ    16
#define SEQ     1024
#define M_TOT   (B_SZ * SEQ)     // 16384
#define QKV_N   (3 * DIM)        // 1920
// q pre-scale: DIM^-0.5 * log2(e), folded into q at QKV epilogue
#define QSCALE  0.0570280394796554f

// ---------------- scratch (device globals) ----------------
__device__ __nv_bfloat16 g_xh[(size_t)M_TOT * DIM];
__device__ __nv_bfloat16 g_xl[(size_t)M_TOT * DIM];
__device__ __nv_bfloat16 g_wqh[(size_t)DIM * QKV_N];   // w_qkv hi  [640][1920] natural
__device__ __nv_bfloat16 g_wql[(size_t)DIM * QKV_N];
__device__ __nv_bfloat16 g_woh[(size_t)DIM * DIM];     // w_out hi  [640][640] natural
__device__ __nv_bfloat16 g_wol[(size_t)DIM * DIM];
// per-head q/k/v, bf16 hi/lo: [B*HEADS][SEQ][64]  (q pre-scaled by QSCALE)
__device__ __nv_bfloat16 g_qh[(size_t)B_SZ * HEADS * SEQ * HD];
__device__ __nv_bfloat16 g_ql[(size_t)B_SZ * HEADS * SEQ * HD];
__device__ __nv_bfloat16 g_kh[(size_t)B_SZ * HEADS * SEQ * HD];
__device__ __nv_bfloat16 g_kl[(size_t)B_SZ * HEADS * SEQ * HD];
__device__ __nv_bfloat16 g_vh[(size_t)B_SZ * HEADS * SEQ * HD];
__device__ __nv_bfloat16 g_vl[(size_t)B_SZ * HEADS * SEQ * HD];
__device__ __nv_bfloat16 g_ah[(size_t)M_TOT * DIM];    // attention out hi (bf16 split)
__device__ __nv_bfloat16 g_al[(size_t)M_TOT * DIM];

// ---------------- helpers ----------------
__device__ __forceinline__ uint32_t smem_u32(const void* p) {
    uint32_t a;
    asm("{ .reg .u64 t; cvta.to.shared.u64 t, %1; cvt.u32.u64 %0, t; }"
        : "=r"(a) : "l"(p));
    return a;
}
__device__ __forceinline__ void ldmatrix_x4(uint32_t* r, uint32_t addr) {
    asm volatile("ldmatrix.sync.aligned.m8n8.x4.shared.b16 {%0,%1,%2,%3}, [%4];"
                 : "=r"(r[0]), "=r"(r[1]), "=r"(r[2]), "=r"(r[3]) : "r"(addr));
}
__device__ __forceinline__ void ldmatrix_x4_trans(uint32_t* r, uint32_t addr) {
    asm volatile("ldmatrix.sync.aligned.m8n8.x4.trans.shared.b16 {%0,%1,%2,%3}, [%4];"
                 : "=r"(r[0]), "=r"(r[1]), "=r"(r[2]), "=r"(r[3]) : "r"(addr));
}
__device__ __forceinline__ void mma_bf16(float* c, const uint32_t* a, const uint32_t* b) {
    asm volatile("mma.sync.aligned.m16n8k16.row.col.f32.bf16.bf16.f32 "
                 "{%0,%1,%2,%3}, {%4,%5,%6,%7}, {%8,%9}, {%0,%1,%2,%3};"
                 : "+f"(c[0]), "+f"(c[1]), "+f"(c[2]), "+f"(c[3])
                 : "r"(a[0]), "r"(a[1]), "r"(a[2]), "r"(a[3]), "r"(b[0]), "r"(b[1]));
}
__device__ __forceinline__ float ex2(float x) {
    float r;
    asm("ex2.approx.ftz.f32 %0, %1;" : "=f"(r) : "f"(x));
    return r;
}
__device__ __forceinline__ void split2(float x, float y, uint32_t& hi, uint32_t& lo) {
    __nv_bfloat162 h;
    h.x = __float2bfloat16(x);
    h.y = __float2bfloat16(y);
    __nv_bfloat162 l;
    l.x = __float2bfloat16(x - __bfloat162float(h.x));
    l.y = __float2bfloat16(y - __bfloat162float(h.y));
    hi = *(uint32_t*)&h;
    lo = *(uint32_t*)&l;
}

#define CPASYNC(dst, src) \
    asm volatile("cp.async.cg.shared.global [%0], [%1], 16;" \
                 :: "r"(dst), "l"(src) : "memory")
#define CPCOMMIT() asm volatile("cp.async.commit_group;" ::: "memory")
#define CPWAIT1()  asm volatile("cp.async.wait_group 1;" ::: "memory")
#define CPWAIT0()  asm volatile("cp.async.wait_group 0;" ::: "memory")

// 64B-row tile (32 bf16), chunk^((row>>1)&3) swizzle — GEMM A tiles (BK=32)
__device__ __forceinline__ uint32_t tile_off(int row, int chunk) {
    return (uint32_t)(row * 64 + 16 * (chunk ^ ((row >> 1) & 3)));
}
// 256B-row tile (128 bf16), chunk^(row&7) swizzle — GEMM B tiles [32k][128n]
__device__ __forceinline__ uint32_t boff(int row, int chunk) {
    return (uint32_t)(row * 256 + 16 * (chunk ^ (row & 7)));
}
// 128B-row tile (64 bf16), chunk^(row&7) swizzle — flash Q/K/V tiles
__device__ __forceinline__ uint32_t foff(int row, int chunk) {
    return (uint32_t)(row * 128 + 16 * (chunk ^ (row & 7)));
}

// ---------------- merged split kernel (float4-vectorized, 1 launch) ----------------
#define NX  (M_TOT * DIM)          // 10485760
#define NWQ (DIM * QKV_N)          // 1228800
#define NWO (DIM * DIM)            // 409600
#define NSPLIT4 ((NX + NWQ + NWO) / 4)

__global__ void split_all(const float* __restrict__ x,
                          const float* __restrict__ wq,
                          const float* __restrict__ wo)
{
    const int i4 = blockIdx.x * 256 + threadIdx.x;
    if (i4 >= NSPLIT4) return;
    const float* src;
    __nv_bfloat16 *hi, *lo;
    int idx = i4 * 4;
    if (idx < NX)            { src = x;  hi = g_xh;  lo = g_xl; }
    else if (idx < NX + NWQ) { idx -= NX;  src = wq; hi = g_wqh; lo = g_wql; }
    else                     { idx -= NX + NWQ; src = wo; hi = g_woh; lo = g_wol; }

    float4 v = *(const float4*)(src + idx);
    uint32_t h0, l0, h1, l1;
    split2(v.x, v.y, h0, l0);
    split2(v.z, v.w, h1, l1);
    uint2 hh; hh.x = h0; hh.y = h1;
    uint2 ll; ll.x = l0; ll.y = l1;
    *(uint2*)(hi + idx) = hh;
    *(uint2*)(lo + idx) = ll;
}

// ---------------- mma.sync split-bf16 GEMM (cp.async 3-stage) ----------------
// C[M,N] = A[M,K] @ W[K,N] + bias. CTA tile MT x 128, BK=32, 8 warps.
// MT=128 (QKV: many waves, max per-CTA efficiency); MT=64 (out-proj: few waves,
// finer grid beats the per-CTA efficiency loss).
#define GS_STAGE 32768
#define GS_AL    8192
#define GS_BH    16384
#define GS_BL    24576
#define GEMM_SMEM (3 * GS_STAGE)

template <bool QKV, int MT>
__global__ __launch_bounds__(256, 2)
void gemm_mma(const __nv_bfloat16* __restrict__ Ah, const __nv_bfloat16* __restrict__ Al,
              const __nv_bfloat16* __restrict__ Bh, const __nv_bfloat16* __restrict__ Bl,
              const float* __restrict__ bias, float* __restrict__ Cout,
              int Ntot, int Ktot)
{
    extern __shared__ char gs[];
    const uint32_t sb = smem_u32(gs);

    constexpr int MI = MT / 32;          // m-frags per warp
    const int tid  = threadIdx.x;
    const int lane = tid & 31;
    const int wid  = tid >> 5;
    const int wm   = wid >> 2;
    const int wn   = wid & 3;
    const int m0   = blockIdx.y * MT;
    const int n0   = blockIdx.x * 128;

    float c[MI][4][4];
    #pragma unroll
    for (int i = 0; i < MI; ++i)
        #pragma unroll
        for (int j = 0; j < 4; ++j)
            #pragma unroll
            for (int t = 0; t < 4; ++t) c[i][j][t] = 0.f;

    auto load_stage = [&](int stage, int k0) {
        const uint32_t s0 = sb + stage * GS_STAGE;
        #pragma unroll
        for (int it = 0; it < MT / 64; ++it) {
            const int idx = it * 256 + tid;
            const int row = idx >> 2;
            const int cc  = idx & 3;
            const uint32_t so = tile_off(row, cc);
            const size_t ga = (size_t)(m0 + row) * Ktot + k0 + cc * 8;
            CPASYNC(s0 + so,         Ah + ga);
            CPASYNC(s0 + GS_AL + so, Al + ga);
        }
        #pragma unroll
        for (int it = 0; it < 2; ++it) {
            const int idx = it * 256 + tid;
            const int row = idx >> 4;
            const int cc  = idx & 15;
            const uint32_t so = boff(row, cc);
            const size_t gb = (size_t)(k0 + row) * Ntot + n0 + cc * 8;
            CPASYNC(s0 + GS_BH + so, Bh + gb);
            CPASYNC(s0 + GS_BL + so, Bl + gb);
        }
        CPCOMMIT();
    };

    const int nk = Ktot / 32;
    load_stage(0, 0);
    load_stage(1, 32);

    const int hilo_b = (lane >> 4) * (GS_BL - GS_BH);
    const int krow_b = lane & 15;

    int st = 0;
    for (int ki = 0; ki < nk; ++ki) {
        if (ki + 2 <= nk) { CPWAIT1(); } else { CPWAIT0(); }
        __syncthreads();
        if (ki + 2 < nk) {
            int st2 = st + 2; if (st2 >= 3) st2 -= 3;
            load_stage(st2, (ki + 2) * 32);
        }

        const uint32_t s0 = sb + st * GS_STAGE;
        #pragma unroll
        for (int ks = 0; ks < 2; ++ks) {
            uint32_t b4[4][4];
            #pragma unroll
            for (int ni = 0; ni < 4; ++ni) {
                const int chn = wn * 4 + ni;
                ldmatrix_x4_trans(b4[ni],
                    s0 + GS_BH + hilo_b + boff(ks * 16 + krow_b, chn));
            }
            #pragma unroll
            for (int mi = 0; mi < MI; ++mi) {
                uint32_t ah[4], al[4];
                const int r = wm * (MT / 2) + mi * 16 + (lane & 15);
                const uint32_t off = tile_off(r, ks * 2 + (lane >> 4));
                ldmatrix_x4(ah, s0 + off);
                ldmatrix_x4(al, s0 + GS_AL + off);
                #pragma unroll
                for (int ni = 0; ni < 4; ++ni) mma_bf16(c[mi][ni], ah, b4[ni] + 0);
                #pragma unroll
                for (int ni = 0; ni < 4; ++ni) mma_bf16(c[mi][ni], ah, b4[ni] + 2);
                #pragma unroll
                for (int ni = 0; ni < 4; ++ni) mma_bf16(c[mi][ni], al, b4[ni] + 0);
            }
        }
        if (++st >= 3) st = 0;
    }

    #pragma unroll
    for (int mi = 0; mi < MI; ++mi) {
        #pragma unroll
        for (int ni = 0; ni < 4; ++ni) {
            const int r0  = m0 + wm * (MT / 2) + mi * 16 + (lane >> 2);
            const int col = n0 + wn * 32 + ni * 8 + (lane & 3) * 2;
            const float b0 = bias[col], b1 = bias[col + 1];
            #pragma unroll
            for (int half = 0; half < 2; ++half) {
                const int r = r0 + half * 8;
                float vx = c[mi][ni][half * 2 + 0] + b0;
                float vy = c[mi][ni][half * 2 + 1] + b1;
                if (QKV) {
                    const int bb  = r >> 10;
                    const int iq  = r & 1023;
                    const int sel = col / DIM;
                    const int nc  = col - sel * DIM;
                    const int h   = nc >> 6;
                    const int d   = nc & 63;
                    if (sel == 0) { vx *= QSCALE; vy *= QSCALE; }
                    __nv_bfloat16* dh = (sel == 0) ? g_qh : (sel == 1) ? g_kh : g_vh;
                    __nv_bfloat16* dl = (sel == 0) ? g_ql : (sel == 1) ? g_kl : g_vl;
                    const size_t idx = (((size_t)(bb * HEADS + h)) * SEQ + iq) * HD + d;
                    uint32_t hi, lo;
                    split2(vx, vy, hi, lo);
                    *(uint32_t*)(dh + idx) = hi;
                    *(uint32_t*)(dl + idx) = lo;
                } else {
                    float2 v; v.x = vx; v.y = vy;
                    *(float2*)&Cout[(size_t)r * Ntot + col] = v;
                }
            }
        }
    }
}

// ---------------- flash attention with mma.sync (cp.async 2-stage K/V) ----------------
// Deferred l-reduction: per-thread partial l, quad-reduced once in the epilogue.
#define FQH 0
#define FQL 16384
#define FKV 32768
#define FKV_STRIDE 32768
#define FKL_O 8192
#define FVH_O 16384
#define FVL_O 24576
#define FLASH_SMEM (32768 + 2 * FKV_STRIDE)   // 98304

__global__ __launch_bounds__(256, 2)
void flash_mma()
{
    extern __shared__ char fs[];
    const uint32_t sb = smem_u32(fs);
    const int tid  = threadIdx.x;
    const int lane = tid & 31;
    const int wid  = tid >> 5;
    const int bh   = blockIdx.y;
    const int q0   = blockIdx.x * 128;
    const size_t base = (size_t)bh * SEQ * HD;

    auto load_kv = [&](int stage, int kb) {
        const uint32_t s0 = sb + FKV + stage * FKV_STRIDE;
        #pragma unroll
        for (int i = 0; i < 2; ++i) {
            const int idx = i * 256 + tid;
            const int row = idx >> 3, ch = idx & 7;
            const uint32_t so = foff(row, ch);
            const size_t g = base + (size_t)(kb + row) * HD + ch * 8;
            CPASYNC(s0 + so,         g_kh + g);
            CPASYNC(s0 + FKL_O + so, g_kl + g);
            CPASYNC(s0 + FVH_O + so, g_vh + g);
            CPASYNC(s0 + FVL_O + so, g_vl + g);
        }
        CPCOMMIT();
    };

    load_kv(0, 0);
    #pragma unroll
    for (int i = 0; i < 4; ++i) {
        const int idx = i * 256 + tid;
        const int row = idx >> 3, ch = idx & 7;
        const uint32_t so = foff(row, ch);
        const size_t g = base + (size_t)(q0 + row) * HD + ch * 8;
        *(uint4*)(fs + FQH + so) = *(const uint4*)(g_qh + g);
        *(uint4*)(fs + FQL + so) = *(const uint4*)(g_ql + g);
    }

    float O[8][4];
    #pragma unroll
    for (int i = 0; i < 8; ++i)
        #pragma unroll
        for (int t = 0; t < 4; ++t) O[i][t] = 0.f;
    float m0 = -1e30f, m1 = -1e30f;
    float l0 = 0.f, l1 = 0.f;       // per-thread partials (quad-reduced at end)

    const int hilo_k = (lane >> 4) * FKL_O;
    const int hilo_v = (lane >> 4) * (FVL_O - FVH_O);

    const int nkb = SEQ / 64;
    for (int kbi = 0; kbi < nkb; ++kbi) {
        CPWAIT0();
        __syncthreads();
        if (kbi + 1 < nkb) load_kv((kbi + 1) & 1, (kbi + 1) * 64);

        const uint32_t s0 = sb + FKV + (kbi & 1) * FKV_STRIDE;

        float c[8][4];
        #pragma unroll
        for (int i = 0; i < 8; ++i)
            #pragma unroll
            for (int t = 0; t < 4; ++t) c[i][t] = 0.f;

        #pragma unroll
        for (int ks = 0; ks < 4; ++ks) {
            uint32_t qh[4], ql[4];
            {
                const int r  = wid * 16 + (lane & 15);
                const int ch = ks * 2 + (lane >> 4);
                ldmatrix_x4(qh, sb + FQH + foff(r, ch));
                ldmatrix_x4(ql, sb + FQL + foff(r, ch));
            }
            const int lr2 = lane & 7;
            const int lc2 = (lane >> 3) & 1;
            #pragma unroll
            for (int ng = 0; ng < 2; ++ng) {
                uint32_t kb4[4][4];
                #pragma unroll
                for (int j = 0; j < 4; ++j)
                    ldmatrix_x4(kb4[j],
                        s0 + hilo_k + foff((ng * 4 + j) * 8 + lr2, ks * 2 + lc2));
                #pragma unroll
                for (int j = 0; j < 4; ++j) mma_bf16(c[ng*4+j], qh, kb4[j] + 0);
                #pragma unroll
                for (int j = 0; j < 4; ++j) mma_bf16(c[ng*4+j], qh, kb4[j] + 2);
                #pragma unroll
                for (int j = 0; j < 4; ++j) mma_bf16(c[ng*4+j], ql, kb4[j] + 0);
            }
        }

        // online softmax (log2 domain); m needs warp-quad reduction, l does not
        float rm0 = -1e30f, rm1 = -1e30f;
        #pragma unroll
        for (int ni = 0; ni < 8; ++ni) {
            rm0 = fmaxf(rm0, fmaxf(c[ni][0], c[ni][1]));
            rm1 = fmaxf(rm1, fmaxf(c[ni][2], c[ni][3]));
        }
        #pragma unroll
        for (int off = 1; off < 4; off <<= 1) {
            rm0 = fmaxf(rm0, __shfl_xor_sync(0xffffffffu, rm0, off));
            rm1 = fmaxf(rm1, __shfl_xor_sync(0xffffffffu, rm1, off));
        }
        const float mn0 = fmaxf(m0, rm0), mn1 = fmaxf(m1, rm1);
        if (!__all_sync(0xffffffffu, (mn0 == m0) && (mn1 == m1))) {
            const float cor0 = ex2(m0 - mn0), cor1 = ex2(m1 - mn1);
            l0 *= cor0; l1 *= cor1;
            #pragma unroll
            for (int nd = 0; nd < 8; ++nd) {
                O[nd][0] *= cor0; O[nd][1] *= cor0;
                O[nd][2] *= cor1; O[nd][3] *= cor1;
            }
            m0 = mn0; m1 = mn1;
        }

        #pragma unroll
        for (int ni = 0; ni < 8; ++ni) {
            c[ni][0] = ex2(c[ni][0] - m0);
            c[ni][1] = ex2(c[ni][1] - m0);
            c[ni][2] = ex2(c[ni][2] - m1);
            c[ni][3] = ex2(c[ni][3] - m1);
            l0 += c[ni][0] + c[ni][1];     // thread-local partial, no shuffles
            l1 += c[ni][2] + c[ni][3];
        }

        // O += P V
        #pragma unroll
        for (int ks2 = 0; ks2 < 4; ++ks2) {
            uint32_t ph[4], pl[4];
            split2(c[2*ks2][0],   c[2*ks2][1],   ph[0], pl[0]);
            split2(c[2*ks2][2],   c[2*ks2][3],   ph[1], pl[1]);
            split2(c[2*ks2+1][0], c[2*ks2+1][1], ph[2], pl[2]);
            split2(c[2*ks2+1][2], c[2*ks2+1][3], ph[3], pl[3]);
            const int vr = ks2 * 16 + (lane & 15);
            #pragma unroll
            for (int ng = 0; ng < 2; ++ng) {
                uint32_t vb4[4][4];
                #pragma unroll
                for (int j = 0; j < 4; ++j)
                    ldmatrix_x4_trans(vb4[j], s0 + FVH_O + hilo_v + foff(vr, ng * 4 + j));
                #pragma unroll
                for (int j = 0; j < 4; ++j) mma_bf16(O[ng*4+j], ph, vb4[j] + 0);
                #pragma unroll
                for (int j = 0; j < 4; ++j) mma_bf16(O[ng*4+j], ph, vb4[j] + 2);
                #pragma unroll
                for (int j = 0; j < 4; ++j) mma_bf16(O[ng*4+j], pl, vb4[j] + 0);
            }
        }
    }

    // final l reduction over the quad (rows are spread across lanes lane&3)
    #pragma unroll
    for (int off = 1; off < 4; off <<= 1) {
        l0 += __shfl_xor_sync(0xffffffffu, l0, off);
        l1 += __shfl_xor_sync(0xffffffffu, l1, off);
    }

    // epilogue
    const float inv0 = 1.f / l0, inv1 = 1.f / l1;
    const int b = bh / HEADS;
    const int h = bh - b * HEADS;
    const int r0 = q0 + wid * 16 + (lane >> 2);
    #pragma unroll
    for (int nd = 0; nd < 8; ++nd) {
        const int col = h * HD + nd * 8 + (lane & 3) * 2;
        uint32_t hi, lo;
        split2(O[nd][0] * inv0, O[nd][1] * inv0, hi, lo);
        size_t idx = ((size_t)(b * SEQ + r0)) * DIM + col;
        *(uint32_t*)(g_ah + idx) = hi;
        *(uint32_t*)(g_al + idx) = lo;
        split2(O[nd][2] * inv1, O[nd][3] * inv1, hi, lo);
        idx = ((size_t)(b * SEQ + r0 + 8)) * DIM + col;
        *(uint32_t*)(g_ah + idx) = hi;
        *(uint32_t*)(g_al + idx) = lo;
    }
}

// ---------------- launch ----------------
extern "C" void kernel_launch(void* const* d_in, const int* in_sizes, int n_in,
                              void* d_out, int out_size)
{
    const float* x     = (const float*)d_in[0];
    const float* w_qkv = (const float*)d_in[1];
    const float* b_qkv = (const float*)d_in[2];
    const float* w_out = (const float*)d_in[3];
    const float* b_out = (const float*)d_in[4];
    float* out = (float*)d_out;

    __nv_bfloat16 *xh, *xl, *wqh, *wql, *woh, *wol, *ah, *al;
    cudaGetSymbolAddress((void**)&xh,  g_xh);
    cudaGetSymbolAddress((void**)&xl,  g_xl);
    cudaGetSymbolAddress((void**)&wqh, g_wqh);
    cudaGetSymbolAddress((void**)&wql, g_wql);
    cudaGetSymbolAddress((void**)&woh, g_woh);
    cudaGetSymbolAddress((void**)&wol, g_wol);
    cudaGetSymbolAddress((void**)&ah,  g_ah);
    cudaGetSymbolAddress((void**)&al,  g_al);

    cudaFuncSetAttribute((const void*)gemm_mma<true, 128>,
                         cudaFuncAttributeMaxDynamicSharedMemorySize, GEMM_SMEM);
    cudaFuncSetAttribute((const void*)gemm_mma<false, 64>,
                         cudaFuncAttributeMaxDynamicSharedMemorySize, GEMM_SMEM);
    cudaFuncSetAttribute(flash_mma, cudaFuncAttributeMaxDynamicSharedMemorySize, FLASH_SMEM);

    // 0) all fp32 -> bf16 hi/lo splits in one vectorized launch
    split_all<<<(NSPLIT4 + 255) / 256, 256>>>(x, w_qkv, w_out);

    // 1) QKV GEMM (128M tiles — high per-CTA efficiency, many waves) -> q/k/v
    gemm_mma<true, 128><<<dim3(QKV_N / 128, M_TOT / 128), 256, GEMM_SMEM>>>(
        xh, xl, wqh, wql, b_qkv, nullptr, QKV_N, DIM);

    // 2) flash attention (HMMA, log2 softmax, deferred l-reduction) -> g_ah/g_al
    flash_mma<<<dim3(SEQ / 128, B_SZ * HEADS), 256, FLASH_SMEM>>>();

    // 3) out projection (64M tiles — few waves, finer grid wins) -> d_out
    gemm_mma<false, 64><<<dim3(DIM / 128, M_TOT / 64), 256, GEMM_SMEM>>>(
        ah, al, woh, wol, b_out, out, DIM, DIM);
}

// round 15
// speedup vs baseline: 1.0850x; 1.0652x over previous
#include <cuda_runtime.h>
#include <cuda_bf16.h>
#include <cstdint>

#define DIM     640
#define HEADS   10
#define HD      64
#define B_SZ    16
#define SEQ     1024
#define M_TOT   (B_SZ * SEQ)     // 16384
#define QKV_N   (3 * DIM)        // 1920
// q pre-scale: DIM^-0.5 * log2(e), folded into q at QKV epilogue
#define QSCALE  0.0570280394796554f

// ---------------- scratch (device globals) ----------------
__device__ __nv_bfloat16 g_xh[(size_t)M_TOT * DIM];
__device__ __nv_bfloat16 g_xl[(size_t)M_TOT * DIM];
__device__ __nv_bfloat16 g_wqh[(size_t)DIM * QKV_N];   // w_qkv hi  [640][1920] natural
__device__ __nv_bfloat16 g_wql[(size_t)DIM * QKV_N];
__device__ __nv_bfloat16 g_woh[(size_t)DIM * DIM];     // w_out hi  [640][640] natural
__device__ __nv_bfloat16 g_wol[(size_t)DIM * DIM];
// per-head q/k/v, bf16: [B*HEADS][SEQ][64]  (q pre-scaled by QSCALE, hi only)
__device__ __nv_bfloat16 g_qh[(size_t)B_SZ * HEADS * SEQ * HD];
__device__ __nv_bfloat16 g_kh[(size_t)B_SZ * HEADS * SEQ * HD];
__device__ __nv_bfloat16 g_kl[(size_t)B_SZ * HEADS * SEQ * HD];
__device__ __nv_bfloat16 g_vh[(size_t)B_SZ * HEADS * SEQ * HD];
__device__ __nv_bfloat16 g_vl[(size_t)B_SZ * HEADS * SEQ * HD];
__device__ __nv_bfloat16 g_ah[(size_t)M_TOT * DIM];    // attention out hi (bf16 split)
__device__ __nv_bfloat16 g_al[(size_t)M_TOT * DIM];

// ---------------- helpers ----------------
__device__ __forceinline__ uint32_t smem_u32(const void* p) {
    uint32_t a;
    asm("{ .reg .u64 t; cvta.to.shared.u64 t, %1; cvt.u32.u64 %0, t; }"
        : "=r"(a) : "l"(p));
    return a;
}
__device__ __forceinline__ void ldmatrix_x4(uint32_t* r, uint32_t addr) {
    asm volatile("ldmatrix.sync.aligned.m8n8.x4.shared.b16 {%0,%1,%2,%3}, [%4];"
                 : "=r"(r[0]), "=r"(r[1]), "=r"(r[2]), "=r"(r[3]) : "r"(addr));
}
__device__ __forceinline__ void ldmatrix_x4_trans(uint32_t* r, uint32_t addr) {
    asm volatile("ldmatrix.sync.aligned.m8n8.x4.trans.shared.b16 {%0,%1,%2,%3}, [%4];"
                 : "=r"(r[0]), "=r"(r[1]), "=r"(r[2]), "=r"(r[3]) : "r"(addr));
}
__device__ __forceinline__ void mma_bf16(float* c, const uint32_t* a, const uint32_t* b) {
    asm volatile("mma.sync.aligned.m16n8k16.row.col.f32.bf16.bf16.f32 "
                 "{%0,%1,%2,%3}, {%4,%5,%6,%7}, {%8,%9}, {%0,%1,%2,%3};"
                 : "+f"(c[0]), "+f"(c[1]), "+f"(c[2]), "+f"(c[3])
                 : "r"(a[0]), "r"(a[1]), "r"(a[2]), "r"(a[3]), "r"(b[0]), "r"(b[1]));
}
__device__ __forceinline__ float ex2(float x) {
    float r;
    asm("ex2.approx.ftz.f32 %0, %1;" : "=f"(r) : "f"(x));
    return r;
}
__device__ __forceinline__ void split2(float x, float y, uint32_t& hi, uint32_t& lo) {
    __nv_bfloat162 h;
    h.x = __float2bfloat16(x);
    h.y = __float2bfloat16(y);
    __nv_bfloat162 l;
    l.x = __float2bfloat16(x - __bfloat162float(h.x));
    l.y = __float2bfloat16(y - __bfloat162float(h.y));
    hi = *(uint32_t*)&h;
    lo = *(uint32_t*)&l;
}

#define CPASYNC(dst, src) \
    asm volatile("cp.async.cg.shared.global [%0], [%1], 16;" \
                 :: "r"(dst), "l"(src) : "memory")
#define CPCOMMIT() asm volatile("cp.async.commit_group;" ::: "memory")
#define CPWAIT1()  asm volatile("cp.async.wait_group 1;" ::: "memory")
#define CPWAIT0()  asm volatile("cp.async.wait_group 0;" ::: "memory")

// 64B-row tile (32 bf16), chunk^((row>>1)&3) swizzle — GEMM A tiles (BK=32)
__device__ __forceinline__ uint32_t tile_off(int row, int chunk) {
    return (uint32_t)(row * 64 + 16 * (chunk ^ ((row >> 1) & 3)));
}
// 256B-row tile (128 bf16), chunk^(row&7) swizzle — GEMM B tiles [32k][128n]
__device__ __forceinline__ uint32_t boff(int row, int chunk) {
    return (uint32_t)(row * 256 + 16 * (chunk ^ (row & 7)));
}
// 128B-row tile (64 bf16), chunk^(row&7) swizzle — flash Q/K/V tiles
__device__ __forceinline__ uint32_t foff(int row, int chunk) {
    return (uint32_t)(row * 128 + 16 * (chunk ^ (row & 7)));
}

// ---------------- merged split kernel (float4-vectorized, 1 launch) ----------------
#define NX  (M_TOT * DIM)          // 10485760
#define NWQ (DIM * QKV_N)          // 1228800
#define NWO (DIM * DIM)            // 409600
#define NSPLIT4 ((NX + NWQ + NWO) / 4)

__global__ void split_all(const float* __restrict__ x,
                          const float* __restrict__ wq,
                          const float* __restrict__ wo)
{
    const int i4 = blockIdx.x * 256 + threadIdx.x;
    if (i4 >= NSPLIT4) return;
    const float* src;
    __nv_bfloat16 *hi, *lo;
    int idx = i4 * 4;
    if (idx < NX)            { src = x;  hi = g_xh;  lo = g_xl; }
    else if (idx < NX + NWQ) { idx -= NX;  src = wq; hi = g_wqh; lo = g_wql; }
    else                     { idx -= NX + NWQ; src = wo; hi = g_woh; lo = g_wol; }

    float4 v = *(const float4*)(src + idx);
    uint32_t h0, l0, h1, l1;
    split2(v.x, v.y, h0, l0);
    split2(v.z, v.w, h1, l1);
    uint2 hh; hh.x = h0; hh.y = h1;
    uint2 ll; ll.x = l0; ll.y = l1;
    *(uint2*)(hi + idx) = hh;
    *(uint2*)(lo + idx) = ll;
}

// ---------------- mma.sync split-bf16 GEMM (cp.async 3-stage) ----------------
// C[M,N] = A[M,K] @ W[K,N] + bias. CTA tile MT x 128, BK=32, 8 warps.
// MT=128 (QKV: many waves); MT=64 (out-proj: few waves, finer grid wins).
#define GS_STAGE 32768
#define GS_AL    8192
#define GS_BH    16384
#define GS_BL    24576
#define GEMM_SMEM (3 * GS_STAGE)

template <bool QKV, int MT>
__global__ __launch_bounds__(256, 2)
void gemm_mma(const __nv_bfloat16* __restrict__ Ah, const __nv_bfloat16* __restrict__ Al,
              const __nv_bfloat16* __restrict__ Bh, const __nv_bfloat16* __restrict__ Bl,
              const float* __restrict__ bias, float* __restrict__ Cout,
              int Ntot, int Ktot)
{
    extern __shared__ char gs[];
    const uint32_t sb = smem_u32(gs);

    constexpr int MI = MT / 32;          // m-frags per warp
    const int tid  = threadIdx.x;
    const int lane = tid & 31;
    const int wid  = tid >> 5;
    const int wm   = wid >> 2;
    const int wn   = wid & 3;
    const int m0   = blockIdx.y * MT;
    const int n0   = blockIdx.x * 128;

    float c[MI][4][4];
    #pragma unroll
    for (int i = 0; i < MI; ++i)
        #pragma unroll
        for (int j = 0; j < 4; ++j)
            #pragma unroll
            for (int t = 0; t < 4; ++t) c[i][j][t] = 0.f;

    auto load_stage = [&](int stage, int k0) {
        const uint32_t s0 = sb + stage * GS_STAGE;
        #pragma unroll
        for (int it = 0; it < MT / 64; ++it) {
            const int idx = it * 256 + tid;
            const int row = idx >> 2;
            const int cc  = idx & 3;
            const uint32_t so = tile_off(row, cc);
            const size_t ga = (size_t)(m0 + row) * Ktot + k0 + cc * 8;
            CPASYNC(s0 + so,         Ah + ga);
            CPASYNC(s0 + GS_AL + so, Al + ga);
        }
        #pragma unroll
        for (int it = 0; it < 2; ++it) {
            const int idx = it * 256 + tid;
            const int row = idx >> 4;
            const int cc  = idx & 15;
            const uint32_t so = boff(row, cc);
            const size_t gb = (size_t)(k0 + row) * Ntot + n0 + cc * 8;
            CPASYNC(s0 + GS_BH + so, Bh + gb);
            CPASYNC(s0 + GS_BL + so, Bl + gb);
        }
        CPCOMMIT();
    };

    const int nk = Ktot / 32;
    load_stage(0, 0);
    load_stage(1, 32);

    const int hilo_b = (lane >> 4) * (GS_BL - GS_BH);
    const int krow_b = lane & 15;

    int st = 0;
    for (int ki = 0; ki < nk; ++ki) {
        if (ki + 2 <= nk) { CPWAIT1(); } else { CPWAIT0(); }
        __syncthreads();
        if (ki + 2 < nk) {
            int st2 = st + 2; if (st2 >= 3) st2 -= 3;
            load_stage(st2, (ki + 2) * 32);
        }

        const uint32_t s0 = sb + st * GS_STAGE;
        #pragma unroll
        for (int ks = 0; ks < 2; ++ks) {
            uint32_t b4[4][4];
            #pragma unroll
            for (int ni = 0; ni < 4; ++ni) {
                const int chn = wn * 4 + ni;
                ldmatrix_x4_trans(b4[ni],
                    s0 + GS_BH + hilo_b + boff(ks * 16 + krow_b, chn));
            }
            #pragma unroll
            for (int mi = 0; mi < MI; ++mi) {
                uint32_t ah[4], al[4];
                const int r = wm * (MT / 2) + mi * 16 + (lane & 15);
                const uint32_t off = tile_off(r, ks * 2 + (lane >> 4));
                ldmatrix_x4(ah, s0 + off);
                ldmatrix_x4(al, s0 + GS_AL + off);
                #pragma unroll
                for (int ni = 0; ni < 4; ++ni) mma_bf16(c[mi][ni], ah, b4[ni] + 0);
                #pragma unroll
                for (int ni = 0; ni < 4; ++ni) mma_bf16(c[mi][ni], ah, b4[ni] + 2);
                #pragma unroll
                for (int ni = 0; ni < 4; ++ni) mma_bf16(c[mi][ni], al, b4[ni] + 0);
            }
        }
        if (++st >= 3) st = 0;
    }

    #pragma unroll
    for (int mi = 0; mi < MI; ++mi) {
        #pragma unroll
        for (int ni = 0; ni < 4; ++ni) {
            const int r0  = m0 + wm * (MT / 2) + mi * 16 + (lane >> 2);
            const int col = n0 + wn * 32 + ni * 8 + (lane & 3) * 2;
            const float b0 = bias[col], b1 = bias[col + 1];
            #pragma unroll
            for (int half = 0; half < 2; ++half) {
                const int r = r0 + half * 8;
                float vx = c[mi][ni][half * 2 + 0] + b0;
                float vy = c[mi][ni][half * 2 + 1] + b1;
                if (QKV) {
                    const int bb  = r >> 10;
                    const int iq  = r & 1023;
                    const int sel = col / DIM;
                    const int nc  = col - sel * DIM;
                    const int h   = nc >> 6;
                    const int d   = nc & 63;
                    const size_t idx = (((size_t)(bb * HEADS + h)) * SEQ + iq) * HD + d;
                    uint32_t hi, lo;
                    if (sel == 0) {
                        vx *= QSCALE; vy *= QSCALE;
                        split2(vx, vy, hi, lo);
                        *(uint32_t*)(g_qh + idx) = hi;       // q: hi only
                    } else if (sel == 1) {
                        split2(vx, vy, hi, lo);
                        *(uint32_t*)(g_kh + idx) = hi;
                        *(uint32_t*)(g_kl + idx) = lo;
                    } else {
                        split2(vx, vy, hi, lo);
                        *(uint32_t*)(g_vh + idx) = hi;
                        *(uint32_t*)(g_vl + idx) = lo;
                    }
                } else {
                    float2 v; v.x = vx; v.y = vy;
                    *(float2*)&Cout[(size_t)r * Ntot + col] = v;
                }
            }
        }
    }
}

// ---------------- flash attention with mma.sync (cp.async 2-stage K/V) ----------------
// S = qh*(kh+kl)  (2 terms; ql term dropped, error ~3e-4).  PV keeps 3 terms.
#define FQH 0
#define FKV 32768
#define FKV_STRIDE 32768
#define FKL_O 8192
#define FVH_O 16384
#define FVL_O 24576
#define FLASH_SMEM (32768 + 2 * FKV_STRIDE)   // 98304

__global__ __launch_bounds__(256, 2)
void flash_mma()
{
    extern __shared__ char fs[];
    const uint32_t sb = smem_u32(fs);
    const int tid  = threadIdx.x;
    const int lane = tid & 31;
    const int wid  = tid >> 5;
    const int bh   = blockIdx.y;
    const int q0   = blockIdx.x * 128;
    const size_t base = (size_t)bh * SEQ * HD;

    auto load_kv = [&](int stage, int kb) {
        const uint32_t s0 = sb + FKV + stage * FKV_STRIDE;
        #pragma unroll
        for (int i = 0; i < 2; ++i) {
            const int idx = i * 256 + tid;
            const int row = idx >> 3, ch = idx & 7;
            const uint32_t so = foff(row, ch);
            const size_t g = base + (size_t)(kb + row) * HD + ch * 8;
            CPASYNC(s0 + so,         g_kh + g);
            CPASYNC(s0 + FKL_O + so, g_kl + g);
            CPASYNC(s0 + FVH_O + so, g_vh + g);
            CPASYNC(s0 + FVL_O + so, g_vl + g);
        }
        CPCOMMIT();
    };

    load_kv(0, 0);
    // stage Q hi: 128 rows x 8 chunks = 1024 uint4 -> 4 iterations of 256 thr
    #pragma unroll
    for (int i = 0; i < 4; ++i) {
        const int idx = i * 256 + tid;         // 0..1023
        const int row = idx >> 3, ch = idx & 7;
        const uint32_t so = foff(row, ch);
        const size_t g = base + (size_t)(q0 + row) * HD + ch * 8;
        *(uint4*)(fs + FQH + so) = *(const uint4*)(g_qh + g);
    }

    float O[8][4];
    #pragma unroll
    for (int i = 0; i < 8; ++i)
        #pragma unroll
        for (int t = 0; t < 4; ++t) O[i][t] = 0.f;
    float m0 = -1e30f, m1 = -1e30f, l0 = 0.f, l1 = 0.f;

    const int hilo_k = (lane >> 4) * FKL_O;
    const int hilo_v = (lane >> 4) * (FVL_O - FVH_O);

    const int nkb = SEQ / 64;
    for (int kbi = 0; kbi < nkb; ++kbi) {
        CPWAIT0();
        __syncthreads();
        if (kbi + 1 < nkb) load_kv((kbi + 1) & 1, (kbi + 1) * 64);

        const uint32_t s0 = sb + FKV + (kbi & 1) * FKV_STRIDE;

        float c[8][4];
        #pragma unroll
        for (int i = 0; i < 8; ++i)
            #pragma unroll
            for (int t = 0; t < 4; ++t) c[i][t] = 0.f;

        #pragma unroll
        for (int ks = 0; ks < 4; ++ks) {
            uint32_t qh[4];
            {
                const int r  = wid * 16 + (lane & 15);
                const int ch = ks * 2 + (lane >> 4);
                ldmatrix_x4(qh, sb + FQH + foff(r, ch));
            }
            const int lr2 = lane & 7;
            const int lc2 = (lane >> 3) & 1;
            #pragma unroll
            for (int ng = 0; ng < 2; ++ng) {
                uint32_t kb4[4][4];
                #pragma unroll
                for (int j = 0; j < 4; ++j)
                    ldmatrix_x4(kb4[j],
                        s0 + hilo_k + foff((ng * 4 + j) * 8 + lr2, ks * 2 + lc2));
                #pragma unroll
                for (int j = 0; j < 4; ++j) mma_bf16(c[ng*4+j], qh, kb4[j] + 0);
                #pragma unroll
                for (int j = 0; j < 4; ++j) mma_bf16(c[ng*4+j], qh, kb4[j] + 2);
            }
        }

        // online softmax (log2 domain)
        float rm0 = -1e30f, rm1 = -1e30f;
        #pragma unroll
        for (int ni = 0; ni < 8; ++ni) {
            rm0 = fmaxf(rm0, fmaxf(c[ni][0], c[ni][1]));
            rm1 = fmaxf(rm1, fmaxf(c[ni][2], c[ni][3]));
        }
        #pragma unroll
        for (int off = 1; off < 4; off <<= 1) {
            rm0 = fmaxf(rm0, __shfl_xor_sync(0xffffffffu, rm0, off));
            rm1 = fmaxf(rm1, __shfl_xor_sync(0xffffffffu, rm1, off));
        }
        const float mn0 = fmaxf(m0, rm0), mn1 = fmaxf(m1, rm1);
        if (!__all_sync(0xffffffffu, (mn0 == m0) && (mn1 == m1))) {
            const float cor0 = ex2(m0 - mn0), cor1 = ex2(m1 - mn1);
            l0 *= cor0; l1 *= cor1;
            #pragma unroll
            for (int nd = 0; nd < 8; ++nd) {
                O[nd][0] *= cor0; O[nd][1] *= cor0;
                O[nd][2] *= cor1; O[nd][3] *= cor1;
            }
            m0 = mn0; m1 = mn1;
        }

        float rs0 = 0.f, rs1 = 0.f;
        #pragma unroll
        for (int ni = 0; ni < 8; ++ni) {
            c[ni][0] = ex2(c[ni][0] - m0);
            c[ni][1] = ex2(c[ni][1] - m0);
            c[ni][2] = ex2(c[ni][2] - m1);
            c[ni][3] = ex2(c[ni][3] - m1);
            rs0 += c[ni][0] + c[ni][1];
            rs1 += c[ni][2] + c[ni][3];
        }
        #pragma unroll
        for (int off = 1; off < 4; off <<= 1) {
            rs0 += __shfl_xor_sync(0xffffffffu, rs0, off);
            rs1 += __shfl_xor_sync(0xffffffffu, rs1, off);
        }
        l0 += rs0;
        l1 += rs1;

        // O += P V (3 terms — pl·vh is load-bearing at the 1e-3 threshold)
        #pragma unroll
        for (int ks2 = 0; ks2 < 4; ++ks2) {
            uint32_t ph[4], pl[4];
            split2(c[2*ks2][0],   c[2*ks2][1],   ph[0], pl[0]);
            split2(c[2*ks2][2],   c[2*ks2][3],   ph[1], pl[1]);
            split2(c[2*ks2+1][0], c[2*ks2+1][1], ph[2], pl[2]);
            split2(c[2*ks2+1][2], c[2*ks2+1][3], ph[3], pl[3]);
            const int vr = ks2 * 16 + (lane & 15);
            #pragma unroll
            for (int ng = 0; ng < 2; ++ng) {
                uint32_t vb4[4][4];
                #pragma unroll
                for (int j = 0; j < 4; ++j)
                    ldmatrix_x4_trans(vb4[j], s0 + FVH_O + hilo_v + foff(vr, ng * 4 + j));
                #pragma unroll
                for (int j = 0; j < 4; ++j) mma_bf16(O[ng*4+j], ph, vb4[j] + 0);
                #pragma unroll
                for (int j = 0; j < 4; ++j) mma_bf16(O[ng*4+j], ph, vb4[j] + 2);
                #pragma unroll
                for (int j = 0; j < 4; ++j) mma_bf16(O[ng*4+j], pl, vb4[j] + 0);
            }
        }
    }

    // epilogue
    const float inv0 = 1.f / l0, inv1 = 1.f / l1;
    const int b = bh / HEADS;
    const int h = bh - b * HEADS;
    const int r0 = q0 + wid * 16 + (lane >> 2);
    #pragma unroll
    for (int nd = 0; nd < 8; ++nd) {
        const int col = h * HD + nd * 8 + (lane & 3) * 2;
        uint32_t hi, lo;
        split2(O[nd][0] * inv0, O[nd][1] * inv0, hi, lo);
        size_t idx = ((size_t)(b * SEQ + r0)) * DIM + col;
        *(uint32_t*)(g_ah + idx) = hi;
        *(uint32_t*)(g_al + idx) = lo;
        split2(O[nd][2] * inv1, O[nd][3] * inv1, hi, lo);
        idx = ((size_t)(b * SEQ + r0 + 8)) * DIM + col;
        *(uint32_t*)(g_ah + idx) = hi;
        *(uint32_t*)(g_al + idx) = lo;
    }
}

// ---------------- launch ----------------
extern "C" void kernel_launch(void* const* d_in, const int* in_sizes, int n_in,
                              void* d_out, int out_size)
{
    const float* x     = (const float*)d_in[0];
    const float* w_qkv = (const float*)d_in[1];
    const float* b_qkv = (const float*)d_in[2];
    const float* w_out = (const float*)d_in[3];
    const float* b_out = (const float*)d_in[4];
    float* out = (float*)d_out;

    __nv_bfloat16 *xh, *xl, *wqh, *wql, *woh, *wol, *ah, *al;
    cudaGetSymbolAddress((void**)&xh,  g_xh);
    cudaGetSymbolAddress((void**)&xl,  g_xl);
    cudaGetSymbolAddress((void**)&wqh, g_wqh);
    cudaGetSymbolAddress((void**)&wql, g_wql);
    cudaGetSymbolAddress((void**)&woh, g_woh);
    cudaGetSymbolAddress((void**)&wol, g_wol);
    cudaGetSymbolAddress((void**)&ah,  g_ah);
    cudaGetSymbolAddress((void**)&al,  g_al);

    cudaFuncSetAttribute((const void*)gemm_mma<true, 128>,
                         cudaFuncAttributeMaxDynamicSharedMemorySize, GEMM_SMEM);
    cudaFuncSetAttribute((const void*)gemm_mma<false, 64>,
                         cudaFuncAttributeMaxDynamicSharedMemorySize, GEMM_SMEM);
    cudaFuncSetAttribute(flash_mma, cudaFuncAttributeMaxDynamicSharedMemorySize, FLASH_SMEM);

    // 0) all fp32 -> bf16 hi/lo splits in one vectorized launch
    split_all<<<(NSPLIT4 + 255) / 256, 256>>>(x, w_qkv, w_out);

    // 1) QKV GEMM (128M tiles) -> q hi, k/v hi+lo
    gemm_mma<true, 128><<<dim3(QKV_N / 128, M_TOT / 128), 256, GEMM_SMEM>>>(
        xh, xl, wqh, wql, b_qkv, nullptr, QKV_N, DIM);

    // 2) flash attention (HMMA, 2-term S) -> g_ah/g_al
    flash_mma<<<dim3(SEQ / 128, B_SZ * HEADS), 256, FLASH_SMEM>>>();

    // 3) out projection (64M tiles) -> d_out
    gemm_mma<false, 64><<<dim3(DIM / 128, M_TOT / 64), 256, GEMM_SMEM>>>(
        ah, al, woh, wol, b_out, out, DIM, DIM);
}

// round 16
// speedup vs baseline: 1.4060x; 1.2958x over previous
#include <cuda_runtime.h>
#include <cuda_bf16.h>
#include <cuda_fp16.h>
#include <cstdint>

#define DIM     640
#define HEADS   10
#define HD      64
#define B_SZ    16
#define SEQ     1024
#define M_TOT   (B_SZ * SEQ)     // 16384
#define QKV_N   (3 * DIM)        // 1920
// q pre-scale: DIM^-0.5 * log2(e), folded into q at QKV epilogue
#define QSCALE  0.0570280394796554f

// ---------------- scratch (device globals) ----------------
__device__ __nv_bfloat16 g_xh[(size_t)M_TOT * DIM];
__device__ __nv_bfloat16 g_xl[(size_t)M_TOT * DIM];
__device__ __nv_bfloat16 g_wqh[(size_t)DIM * QKV_N];   // w_qkv hi  [640][1920] natural
__device__ __nv_bfloat16 g_wql[(size_t)DIM * QKV_N];
__device__ __nv_bfloat16 g_woh[(size_t)DIM * DIM];     // w_out hi  [640][640] natural
__device__ __nv_bfloat16 g_wol[(size_t)DIM * DIM];
// per-head q/k/v, fp16 single: [B*HEADS][SEQ][64]  (q pre-scaled by QSCALE)
__device__ __half g_q[(size_t)B_SZ * HEADS * SEQ * HD];
__device__ __half g_k[(size_t)B_SZ * HEADS * SEQ * HD];
__device__ __half g_v[(size_t)B_SZ * HEADS * SEQ * HD];
__device__ __nv_bfloat16 g_ah[(size_t)M_TOT * DIM];    // attention out hi (bf16 split)
__device__ __nv_bfloat16 g_al[(size_t)M_TOT * DIM];

// ---------------- helpers ----------------
__device__ __forceinline__ uint32_t smem_u32(const void* p) {
    uint32_t a;
    asm("{ .reg .u64 t; cvta.to.shared.u64 t, %1; cvt.u32.u64 %0, t; }"
        : "=r"(a) : "l"(p));
    return a;
}
__device__ __forceinline__ void ldmatrix_x4(uint32_t* r, uint32_t addr) {
    asm volatile("ldmatrix.sync.aligned.m8n8.x4.shared.b16 {%0,%1,%2,%3}, [%4];"
                 : "=r"(r[0]), "=r"(r[1]), "=r"(r[2]), "=r"(r[3]) : "r"(addr));
}
__device__ __forceinline__ void ldmatrix_x4_trans(uint32_t* r, uint32_t addr) {
    asm volatile("ldmatrix.sync.aligned.m8n8.x4.trans.shared.b16 {%0,%1,%2,%3}, [%4];"
                 : "=r"(r[0]), "=r"(r[1]), "=r"(r[2]), "=r"(r[3]) : "r"(addr));
}
__device__ __forceinline__ void mma_bf16(float* c, const uint32_t* a, const uint32_t* b) {
    asm volatile("mma.sync.aligned.m16n8k16.row.col.f32.bf16.bf16.f32 "
                 "{%0,%1,%2,%3}, {%4,%5,%6,%7}, {%8,%9}, {%0,%1,%2,%3};"
                 : "+f"(c[0]), "+f"(c[1]), "+f"(c[2]), "+f"(c[3])
                 : "r"(a[0]), "r"(a[1]), "r"(a[2]), "r"(a[3]), "r"(b[0]), "r"(b[1]));
}
__device__ __forceinline__ void mma_fp16(float* c, const uint32_t* a, const uint32_t* b) {
    asm volatile("mma.sync.aligned.m16n8k16.row.col.f32.f16.f16.f32 "
                 "{%0,%1,%2,%3}, {%4,%5,%6,%7}, {%8,%9}, {%0,%1,%2,%3};"
                 : "+f"(c[0]), "+f"(c[1]), "+f"(c[2]), "+f"(c[3])
                 : "r"(a[0]), "r"(a[1]), "r"(a[2]), "r"(a[3]), "r"(b[0]), "r"(b[1]));
}
__device__ __forceinline__ float ex2(float x) {
    float r;
    asm("ex2.approx.ftz.f32 %0, %1;" : "=f"(r) : "f"(x));
    return r;
}
__device__ __forceinline__ uint32_t h2pack(float x, float y) {
    __half2 t = __floats2half2_rn(x, y);
    return *(uint32_t*)&t;
}
__device__ __forceinline__ void split2(float x, float y, uint32_t& hi, uint32_t& lo) {
    __nv_bfloat162 h;
    h.x = __float2bfloat16(x);
    h.y = __float2bfloat16(y);
    __nv_bfloat162 l;
    l.x = __float2bfloat16(x - __bfloat162float(h.x));
    l.y = __float2bfloat16(y - __bfloat162float(h.y));
    hi = *(uint32_t*)&h;
    lo = *(uint32_t*)&l;
}

#define CPASYNC(dst, src) \
    asm volatile("cp.async.cg.shared.global [%0], [%1], 16;" \
                 :: "r"(dst), "l"(src) : "memory")
#define CPCOMMIT() asm volatile("cp.async.commit_group;" ::: "memory")
#define CPWAIT1()  asm volatile("cp.async.wait_group 1;" ::: "memory")
#define CPWAIT0()  asm volatile("cp.async.wait_group 0;" ::: "memory")

// 64B-row tile (32 bf16), chunk^((row>>1)&3) swizzle — GEMM A tiles (BK=32)
__device__ __forceinline__ uint32_t tile_off(int row, int chunk) {
    return (uint32_t)(row * 64 + 16 * (chunk ^ ((row >> 1) & 3)));
}
// 256B-row tile (128 bf16), chunk^(row&7) swizzle — GEMM B tiles [32k][128n]
__device__ __forceinline__ uint32_t boff(int row, int chunk) {
    return (uint32_t)(row * 256 + 16 * (chunk ^ (row & 7)));
}
// 128B-row tile (64 b16), chunk^(row&7) swizzle — flash Q/K/V tiles
__device__ __forceinline__ uint32_t foff(int row, int chunk) {
    return (uint32_t)(row * 128 + 16 * (chunk ^ (row & 7)));
}

// ---------------- merged split kernel (float4-vectorized, 1 launch) ----------------
#define NX  (M_TOT * DIM)          // 10485760
#define NWQ (DIM * QKV_N)          // 1228800
#define NWO (DIM * DIM)            // 409600
#define NSPLIT4 ((NX + NWQ + NWO) / 4)

__global__ void split_all(const float* __restrict__ x,
                          const float* __restrict__ wq,
                          const float* __restrict__ wo)
{
    const int i4 = blockIdx.x * 256 + threadIdx.x;
    if (i4 >= NSPLIT4) return;
    const float* src;
    __nv_bfloat16 *hi, *lo;
    int idx = i4 * 4;
    if (idx < NX)            { src = x;  hi = g_xh;  lo = g_xl; }
    else if (idx < NX + NWQ) { idx -= NX;  src = wq; hi = g_wqh; lo = g_wql; }
    else                     { idx -= NX + NWQ; src = wo; hi = g_woh; lo = g_wol; }

    float4 v = *(const float4*)(src + idx);
    uint32_t h0, l0, h1, l1;
    split2(v.x, v.y, h0, l0);
    split2(v.z, v.w, h1, l1);
    uint2 hh; hh.x = h0; hh.y = h1;
    uint2 ll; ll.x = l0; ll.y = l1;
    *(uint2*)(hi + idx) = hh;
    *(uint2*)(lo + idx) = ll;
}

// ---------------- mma.sync split-bf16 GEMM (cp.async 3-stage) ----------------
// C[M,N] = A[M,K] @ W[K,N] + bias. CTA tile MT x 128, BK=32, 8 warps.
// MT=128 (QKV: many waves); MT=64 (out-proj: few waves, finer grid wins).
#define GS_STAGE 32768
#define GS_AL    8192
#define GS_BH    16384
#define GS_BL    24576
#define GEMM_SMEM (3 * GS_STAGE)

template <bool QKV, int MT>
__global__ __launch_bounds__(256, 2)
void gemm_mma(const __nv_bfloat16* __restrict__ Ah, const __nv_bfloat16* __restrict__ Al,
              const __nv_bfloat16* __restrict__ Bh, const __nv_bfloat16* __restrict__ Bl,
              const float* __restrict__ bias, float* __restrict__ Cout,
              int Ntot, int Ktot)
{
    extern __shared__ char gs[];
    const uint32_t sb = smem_u32(gs);

    constexpr int MI = MT / 32;
    const int tid  = threadIdx.x;
    const int lane = tid & 31;
    const int wid  = tid >> 5;
    const int wm   = wid >> 2;
    const int wn   = wid & 3;
    const int m0   = blockIdx.y * MT;
    const int n0   = blockIdx.x * 128;

    float c[MI][4][4];
    #pragma unroll
    for (int i = 0; i < MI; ++i)
        #pragma unroll
        for (int j = 0; j < 4; ++j)
            #pragma unroll
            for (int t = 0; t < 4; ++t) c[i][j][t] = 0.f;

    auto load_stage = [&](int stage, int k0) {
        const uint32_t s0 = sb + stage * GS_STAGE;
        #pragma unroll
        for (int it = 0; it < MT / 64; ++it) {
            const int idx = it * 256 + tid;
            const int row = idx >> 2;
            const int cc  = idx & 3;
            const uint32_t so = tile_off(row, cc);
            const size_t ga = (size_t)(m0 + row) * Ktot + k0 + cc * 8;
            CPASYNC(s0 + so,         Ah + ga);
            CPASYNC(s0 + GS_AL + so, Al + ga);
        }
        #pragma unroll
        for (int it = 0; it < 2; ++it) {
            const int idx = it * 256 + tid;
            const int row = idx >> 4;
            const int cc  = idx & 15;
            const uint32_t so = boff(row, cc);
            const size_t gb = (size_t)(k0 + row) * Ntot + n0 + cc * 8;
            CPASYNC(s0 + GS_BH + so, Bh + gb);
            CPASYNC(s0 + GS_BL + so, Bl + gb);
        }
        CPCOMMIT();
    };

    const int nk = Ktot / 32;
    load_stage(0, 0);
    load_stage(1, 32);

    const int hilo_b = (lane >> 4) * (GS_BL - GS_BH);
    const int krow_b = lane & 15;

    int st = 0;
    for (int ki = 0; ki < nk; ++ki) {
        if (ki + 2 <= nk) { CPWAIT1(); } else { CPWAIT0(); }
        __syncthreads();
        if (ki + 2 < nk) {
            int st2 = st + 2; if (st2 >= 3) st2 -= 3;
            load_stage(st2, (ki + 2) * 32);
        }

        const uint32_t s0 = sb + st * GS_STAGE;
        #pragma unroll
        for (int ks = 0; ks < 2; ++ks) {
            uint32_t b4[4][4];
            #pragma unroll
            for (int ni = 0; ni < 4; ++ni) {
                const int chn = wn * 4 + ni;
                ldmatrix_x4_trans(b4[ni],
                    s0 + GS_BH + hilo_b + boff(ks * 16 + krow_b, chn));
            }
            #pragma unroll
            for (int mi = 0; mi < MI; ++mi) {
                uint32_t ah[4], al[4];
                const int r = wm * (MT / 2) + mi * 16 + (lane & 15);
                const uint32_t off = tile_off(r, ks * 2 + (lane >> 4));
                ldmatrix_x4(ah, s0 + off);
                ldmatrix_x4(al, s0 + GS_AL + off);
                #pragma unroll
                for (int ni = 0; ni < 4; ++ni) mma_bf16(c[mi][ni], ah, b4[ni] + 0);
                #pragma unroll
                for (int ni = 0; ni < 4; ++ni) mma_bf16(c[mi][ni], ah, b4[ni] + 2);
                #pragma unroll
                for (int ni = 0; ni < 4; ++ni) mma_bf16(c[mi][ni], al, b4[ni] + 0);
            }
        }
        if (++st >= 3) st = 0;
    }

    #pragma unroll
    for (int mi = 0; mi < MI; ++mi) {
        #pragma unroll
        for (int ni = 0; ni < 4; ++ni) {
            const int r0  = m0 + wm * (MT / 2) + mi * 16 + (lane >> 2);
            const int col = n0 + wn * 32 + ni * 8 + (lane & 3) * 2;
            const float b0 = bias[col], b1 = bias[col + 1];
            #pragma unroll
            for (int half = 0; half < 2; ++half) {
                const int r = r0 + half * 8;
                float vx = c[mi][ni][half * 2 + 0] + b0;
                float vy = c[mi][ni][half * 2 + 1] + b1;
                if (QKV) {
                    const int bb  = r >> 10;
                    const int iq  = r & 1023;
                    const int sel = col / DIM;
                    const int nc  = col - sel * DIM;
                    const int h   = nc >> 6;
                    const int d   = nc & 63;
                    const size_t idx = (((size_t)(bb * HEADS + h)) * SEQ + iq) * HD + d;
                    if (sel == 0) {
                        *(uint32_t*)(g_q + idx) = h2pack(vx * QSCALE, vy * QSCALE);
                    } else if (sel == 1) {
                        *(uint32_t*)(g_k + idx) = h2pack(vx, vy);
                    } else {
                        *(uint32_t*)(g_v + idx) = h2pack(vx, vy);
                    }
                } else {
                    float2 v; v.x = vx; v.y = vy;
                    *(float2*)&Cout[(size_t)r * Ntot + col] = v;
                }
            }
        }
    }
}

// ---------------- flash attention, fp16 single-term (cp.async 2-stage K/V) ----------------
// S = q_fp16 · k_fp16 (1 MMA);  O += p_fp16 · v_fp16 (1 MMA).
// smem: [Q 16K][stage0: K 8K | V 8K][stage1: K 8K | V 8K] = 48KB
#define FQ  0
#define FKV 16384
#define FKV_STRIDE 16384
#define FV_O 8192
#define FLASH_SMEM (16384 + 2 * FKV_STRIDE)   // 49152

__global__ __launch_bounds__(256, 2)
void flash_mma()
{
    extern __shared__ char fs[];
    const uint32_t sb = smem_u32(fs);
    const int tid  = threadIdx.x;
    const int lane = tid & 31;
    const int wid  = tid >> 5;
    const int bh   = blockIdx.y;
    const int q0   = blockIdx.x * 128;
    const size_t base = (size_t)bh * SEQ * HD;

    auto load_kv = [&](int stage, int kb) {
        const uint32_t s0 = sb + FKV + stage * FKV_STRIDE;
        #pragma unroll
        for (int i = 0; i < 2; ++i) {
            const int idx = i * 256 + tid;     // 0..511 (64 rows x 8 chunks)
            const int row = idx >> 3, ch = idx & 7;
            const uint32_t so = foff(row, ch);
            const size_t g = base + (size_t)(kb + row) * HD + ch * 8;
            CPASYNC(s0 + so,        g_k + g);
            CPASYNC(s0 + FV_O + so, g_v + g);
        }
        CPCOMMIT();
    };

    load_kv(0, 0);
    // stage Q fp16: 128 rows x 8 chunks = 1024 uint4 -> 4 iterations
    #pragma unroll
    for (int i = 0; i < 4; ++i) {
        const int idx = i * 256 + tid;
        const int row = idx >> 3, ch = idx & 7;
        const uint32_t so = foff(row, ch);
        const size_t g = base + (size_t)(q0 + row) * HD + ch * 8;
        *(uint4*)(fs + FQ + so) = *(const uint4*)(g_q + g);
    }

    float O[8][4];
    #pragma unroll
    for (int i = 0; i < 8; ++i)
        #pragma unroll
        for (int t = 0; t < 4; ++t) O[i][t] = 0.f;
    float m0 = -1e30f, m1 = -1e30f, l0 = 0.f, l1 = 0.f;

    const int nkb = SEQ / 64;
    for (int kbi = 0; kbi < nkb; ++kbi) {
        CPWAIT0();
        __syncthreads();
        if (kbi + 1 < nkb) load_kv((kbi + 1) & 1, (kbi + 1) * 64);

        const uint32_t s0 = sb + FKV + (kbi & 1) * FKV_STRIDE;

        float c[8][4];
        #pragma unroll
        for (int i = 0; i < 8; ++i)
            #pragma unroll
            for (int t = 0; t < 4; ++t) c[i][t] = 0.f;

        // S = Q K^T : per ks, 1 q-frag + 4 paired k x4-ldmatrix -> 8 MMAs
        #pragma unroll
        for (int ks = 0; ks < 4; ++ks) {
            uint32_t qf[4];
            {
                const int r  = wid * 16 + (lane & 15);
                const int ch = ks * 2 + (lane >> 4);
                ldmatrix_x4(qf, sb + FQ + foff(r, ch));
            }
            #pragma unroll
            for (int jj = 0; jj < 4; ++jj) {
                uint32_t kb4[4];
                const int row = (2 * jj + (lane >> 4)) * 8 + (lane & 7);
                const int ch  = ks * 2 + ((lane >> 3) & 1);
                ldmatrix_x4(kb4, s0 + foff(row, ch));
                mma_fp16(c[2*jj + 0], qf, kb4 + 0);
                mma_fp16(c[2*jj + 1], qf, kb4 + 2);
            }
        }

        // online softmax (log2 domain)
        float rm0 = -1e30f, rm1 = -1e30f;
        #pragma unroll
        for (int ni = 0; ni < 8; ++ni) {
            rm0 = fmaxf(rm0, fmaxf(c[ni][0], c[ni][1]));
            rm1 = fmaxf(rm1, fmaxf(c[ni][2], c[ni][3]));
        }
        #pragma unroll
        for (int off = 1; off < 4; off <<= 1) {
            rm0 = fmaxf(rm0, __shfl_xor_sync(0xffffffffu, rm0, off));
            rm1 = fmaxf(rm1, __shfl_xor_sync(0xffffffffu, rm1, off));
        }
        const float mn0 = fmaxf(m0, rm0), mn1 = fmaxf(m1, rm1);
        if (!__all_sync(0xffffffffu, (mn0 == m0) && (mn1 == m1))) {
            const float cor0 = ex2(m0 - mn0), cor1 = ex2(m1 - mn1);
            l0 *= cor0; l1 *= cor1;
            #pragma unroll
            for (int nd = 0; nd < 8; ++nd) {
                O[nd][0] *= cor0; O[nd][1] *= cor0;
                O[nd][2] *= cor1; O[nd][3] *= cor1;
            }
            m0 = mn0; m1 = mn1;
        }

        float rs0 = 0.f, rs1 = 0.f;
        #pragma unroll
        for (int ni = 0; ni < 8; ++ni) {
            c[ni][0] = ex2(c[ni][0] - m0);
            c[ni][1] = ex2(c[ni][1] - m0);
            c[ni][2] = ex2(c[ni][2] - m1);
            c[ni][3] = ex2(c[ni][3] - m1);
            rs0 += c[ni][0] + c[ni][1];
            rs1 += c[ni][2] + c[ni][3];
        }
        #pragma unroll
        for (int off = 1; off < 4; off <<= 1) {
            rs0 += __shfl_xor_sync(0xffffffffu, rs0, off);
            rs1 += __shfl_xor_sync(0xffffffffu, rs1, off);
        }
        l0 += rs0;
        l1 += rs1;

        // O += P V : per ks2, pack p to fp16 + 4 paired v x4.trans -> 8 MMAs
        #pragma unroll
        for (int ks2 = 0; ks2 < 4; ++ks2) {
            uint32_t pf[4];
            pf[0] = h2pack(c[2*ks2][0],   c[2*ks2][1]);
            pf[1] = h2pack(c[2*ks2][2],   c[2*ks2][3]);
            pf[2] = h2pack(c[2*ks2+1][0], c[2*ks2+1][1]);
            pf[3] = h2pack(c[2*ks2+1][2], c[2*ks2+1][3]);
            #pragma unroll
            for (int jj = 0; jj < 4; ++jj) {
                uint32_t vb4[4];
                const int row = ks2 * 16 + (lane & 15);
                const int ch  = 2 * jj + (lane >> 4);
                ldmatrix_x4_trans(vb4, s0 + FV_O + foff(row, ch));
                mma_fp16(O[2*jj + 0], pf, vb4 + 0);
                mma_fp16(O[2*jj + 1], pf, vb4 + 2);
            }
        }
    }

    // epilogue: bf16 hi/lo out (keeps out-proj 3-term accuracy)
    const float inv0 = 1.f / l0, inv1 = 1.f / l1;
    const int b = bh / HEADS;
    const int h = bh - b * HEADS;
    const int r0 = q0 + wid * 16 + (lane >> 2);
    #pragma unroll
    for (int nd = 0; nd < 8; ++nd) {
        const int col = h * HD + nd * 8 + (lane & 3) * 2;
        uint32_t hi, lo;
        split2(O[nd][0] * inv0, O[nd][1] * inv0, hi, lo);
        size_t idx = ((size_t)(b * SEQ + r0)) * DIM + col;
        *(uint32_t*)(g_ah + idx) = hi;
        *(uint32_t*)(g_al + idx) = lo;
        split2(O[nd][2] * inv1, O[nd][3] * inv1, hi, lo);
        idx = ((size_t)(b * SEQ + r0 + 8)) * DIM + col;
        *(uint32_t*)(g_ah + idx) = hi;
        *(uint32_t*)(g_al + idx) = lo;
    }
}

// ---------------- launch ----------------
extern "C" void kernel_launch(void* const* d_in, const int* in_sizes, int n_in,
                              void* d_out, int out_size)
{
    const float* x     = (const float*)d_in[0];
    const float* w_qkv = (const float*)d_in[1];
    const float* b_qkv = (const float*)d_in[2];
    const float* w_out = (const float*)d_in[3];
    const float* b_out = (const float*)d_in[4];
    float* out = (float*)d_out;

    __nv_bfloat16 *xh, *xl, *wqh, *wql, *woh, *wol, *ah, *al;
    cudaGetSymbolAddress((void**)&xh,  g_xh);
    cudaGetSymbolAddress((void**)&xl,  g_xl);
    cudaGetSymbolAddress((void**)&wqh, g_wqh);
    cudaGetSymbolAddress((void**)&wql, g_wql);
    cudaGetSymbolAddress((void**)&woh, g_woh);
    cudaGetSymbolAddress((void**)&wol, g_wol);
    cudaGetSymbolAddress((void**)&ah,  g_ah);
    cudaGetSymbolAddress((void**)&al,  g_al);

    cudaFuncSetAttribute((const void*)gemm_mma<true, 128>,
                         cudaFuncAttributeMaxDynamicSharedMemorySize, GEMM_SMEM);
    cudaFuncSetAttribute((const void*)gemm_mma<false, 64>,
                         cudaFuncAttributeMaxDynamicSharedMemorySize, GEMM_SMEM);
    cudaFuncSetAttribute(flash_mma, cudaFuncAttributeMaxDynamicSharedMemorySize, FLASH_SMEM);

    // 0) all fp32 -> bf16 hi/lo splits in one vectorized launch
    split_all<<<(NSPLIT4 + 255) / 256, 256>>>(x, w_qkv, w_out);

    // 1) QKV GEMM (3-term bf16, 128M tiles) -> q/k/v fp16 single
    gemm_mma<true, 128><<<dim3(QKV_N / 128, M_TOT / 128), 256, GEMM_SMEM>>>(
        xh, xl, wqh, wql, b_qkv, nullptr, QKV_N, DIM);

    // 2) flash attention (fp16 single-term HMMA) -> g_ah/g_al
    flash_mma<<<dim3(SEQ / 128, B_SZ * HEADS), 256, FLASH_SMEM>>>();

    // 3) out projection (3-term bf16, 64M tiles) -> d_out
    gemm_mma<false, 64><<<dim3(DIM / 128, M_TOT / 64), 256, GEMM_SMEM>>>(
        ah, al, woh, wol, b_out, out, DIM, DIM);
}

// round 17
// speedup vs baseline: 1.7979x; 1.2787x over previous
#include <cuda_runtime.h>
#include <cuda_bf16.h>
#include <cuda_fp16.h>
#include <cstdint>

#define DIM     640
#define HEADS   10
#define HD      64
#define B_SZ    16
#define SEQ     1024
#define M_TOT   (B_SZ * SEQ)     // 16384
#define QKV_N   (3 * DIM)        // 1920
// q pre-scale: DIM^-0.5 * log2(e), folded into q at QKV epilogue
#define QSCALE  0.0570280394796554f

// ---------------- scratch (device globals, all fp16) ----------------
__device__ __half g_x[(size_t)M_TOT * DIM];            // x fp16 single
__device__ __half g_wqh[(size_t)DIM * QKV_N];          // w_qkv hi/lo fp16 [640][1920]
__device__ __half g_wql[(size_t)DIM * QKV_N];
__device__ __half g_woh[(size_t)DIM * DIM];            // w_out hi/lo fp16 [640][640]
__device__ __half g_wol[(size_t)DIM * DIM];
// per-head q/k/v fp16 single: [B*HEADS][SEQ][64]  (q pre-scaled by QSCALE)
__device__ __half g_q[(size_t)B_SZ * HEADS * SEQ * HD];
__device__ __half g_k[(size_t)B_SZ * HEADS * SEQ * HD];
__device__ __half g_v[(size_t)B_SZ * HEADS * SEQ * HD];
__device__ __half g_a[(size_t)M_TOT * DIM];            // attention out fp16 single

// ---------------- helpers ----------------
__device__ __forceinline__ uint32_t smem_u32(const void* p) {
    uint32_t a;
    asm("{ .reg .u64 t; cvta.to.shared.u64 t, %1; cvt.u32.u64 %0, t; }"
        : "=r"(a) : "l"(p));
    return a;
}
__device__ __forceinline__ void ldmatrix_x4(uint32_t* r, uint32_t addr) {
    asm volatile("ldmatrix.sync.aligned.m8n8.x4.shared.b16 {%0,%1,%2,%3}, [%4];"
                 : "=r"(r[0]), "=r"(r[1]), "=r"(r[2]), "=r"(r[3]) : "r"(addr));
}
__device__ __forceinline__ void ldmatrix_x4_trans(uint32_t* r, uint32_t addr) {
    asm volatile("ldmatrix.sync.aligned.m8n8.x4.trans.shared.b16 {%0,%1,%2,%3}, [%4];"
                 : "=r"(r[0]), "=r"(r[1]), "=r"(r[2]), "=r"(r[3]) : "r"(addr));
}
__device__ __forceinline__ void mma_fp16(float* c, const uint32_t* a, const uint32_t* b) {
    asm volatile("mma.sync.aligned.m16n8k16.row.col.f32.f16.f16.f32 "
                 "{%0,%1,%2,%3}, {%4,%5,%6,%7}, {%8,%9}, {%0,%1,%2,%3};"
                 : "+f"(c[0]), "+f"(c[1]), "+f"(c[2]), "+f"(c[3])
                 : "r"(a[0]), "r"(a[1]), "r"(a[2]), "r"(a[3]), "r"(b[0]), "r"(b[1]));
}
__device__ __forceinline__ float ex2(float x) {
    float r;
    asm("ex2.approx.ftz.f32 %0, %1;" : "=f"(r) : "f"(x));
    return r;
}
__device__ __forceinline__ uint32_t h2pack(float x, float y) {
    __half2 t = __floats2half2_rn(x, y);
    return *(uint32_t*)&t;
}
// fp16 hi/lo split of two floats
__device__ __forceinline__ void hsplit2(float x, float y, uint32_t& hi, uint32_t& lo) {
    __half hx = __float2half_rn(x), hy = __float2half_rn(y);
    __half lx = __float2half_rn(x - __half2float(hx));
    __half ly = __float2half_rn(y - __half2float(hy));
    __half2 h; h.x = hx; h.y = hy;
    __half2 l; l.x = lx; l.y = ly;
    hi = *(uint32_t*)&h;
    lo = *(uint32_t*)&l;
}

#define CPASYNC(dst, src) \
    asm volatile("cp.async.cg.shared.global [%0], [%1], 16;" \
                 :: "r"(dst), "l"(src) : "memory")
#define CPCOMMIT() asm volatile("cp.async.commit_group;" ::: "memory")
#define CPWAIT1()  asm volatile("cp.async.wait_group 1;" ::: "memory")
#define CPWAIT0()  asm volatile("cp.async.wait_group 0;" ::: "memory")

// 64B-row tile (32 h16), chunk^((row>>1)&3) swizzle — GEMM A tiles (BK=32)
__device__ __forceinline__ uint32_t tile_off(int row, int chunk) {
    return (uint32_t)(row * 64 + 16 * (chunk ^ ((row >> 1) & 3)));
}
// 256B-row tile (128 h16), chunk^(row&7) swizzle — GEMM B tiles [32k][128n]
__device__ __forceinline__ uint32_t boff(int row, int chunk) {
    return (uint32_t)(row * 256 + 16 * (chunk ^ (row & 7)));
}
// 128B-row tile (64 h16), chunk^(row&7) swizzle — flash Q/K/V tiles
__device__ __forceinline__ uint32_t foff(int row, int chunk) {
    return (uint32_t)(row * 128 + 16 * (chunk ^ (row & 7)));
}

// ---------------- merged split kernel ----------------
#define NX  (M_TOT * DIM)          // 10485760
#define NWQ (DIM * QKV_N)          // 1228800
#define NWO (DIM * DIM)            // 409600
#define NSPLIT4 ((NX + NWQ + NWO) / 4)

__global__ void split_all(const float* __restrict__ x,
                          const float* __restrict__ wq,
                          const float* __restrict__ wo)
{
    const int i4 = blockIdx.x * 256 + threadIdx.x;
    if (i4 >= NSPLIT4) return;
    int idx = i4 * 4;
    if (idx < NX) {
        float4 v = *(const float4*)(x + idx);
        uint2 r;
        r.x = h2pack(v.x, v.y);
        r.y = h2pack(v.z, v.w);
        *(uint2*)(g_x + idx) = r;                      // x: fp16 single
    } else if (idx < NX + NWQ) {
        idx -= NX;
        float4 v = *(const float4*)(wq + idx);
        uint32_t h0, l0, h1, l1;
        hsplit2(v.x, v.y, h0, l0);
        hsplit2(v.z, v.w, h1, l1);
        uint2 hh; hh.x = h0; hh.y = h1;
        uint2 ll; ll.x = l0; ll.y = l1;
        *(uint2*)(g_wqh + idx) = hh;
        *(uint2*)(g_wql + idx) = ll;
    } else {
        idx -= NX + NWQ;
        float4 v = *(const float4*)(wo + idx);
        uint32_t h0, l0, h1, l1;
        hsplit2(v.x, v.y, h0, l0);
        hsplit2(v.z, v.w, h1, l1);
        uint2 hh; hh.x = h0; hh.y = h1;
        uint2 ll; ll.x = l0; ll.y = l1;
        *(uint2*)(g_woh + idx) = hh;
        *(uint2*)(g_wol + idx) = ll;
    }
}

// ---------------- fp16 2-term GEMM (cp.async 3-stage) ----------------
// C[M,N] = A[M,K] @ (Wh+Wl)[K,N] + bias. A fp16 single, W fp16 hi/lo.
// CTA tile MT x 128, BK=32, 8 warps. 2 MMAs per fragment.
// stage: [A 8K][Bh 8K][Bl 8K] = 24KB; 3 stages = 72KB dynamic.
#define GS_STAGE 24576
#define GS_BH    8192
#define GS_BL    16384
#define GEMM_SMEM (3 * GS_STAGE)

template <bool QKV, int MT>
__global__ __launch_bounds__(256, 2)
void gemm_mma(const __half* __restrict__ A,
              const __half* __restrict__ Bh, const __half* __restrict__ Bl,
              const float* __restrict__ bias, float* __restrict__ Cout,
              int Ntot, int Ktot)
{
    extern __shared__ char gs[];
    const uint32_t sb = smem_u32(gs);

    constexpr int MI = MT / 32;
    const int tid  = threadIdx.x;
    const int lane = tid & 31;
    const int wid  = tid >> 5;
    const int wm   = wid >> 2;
    const int wn   = wid & 3;
    const int m0   = blockIdx.y * MT;
    const int n0   = blockIdx.x * 128;

    float c[MI][4][4];
    #pragma unroll
    for (int i = 0; i < MI; ++i)
        #pragma unroll
        for (int j = 0; j < 4; ++j)
            #pragma unroll
            for (int t = 0; t < 4; ++t) c[i][j][t] = 0.f;

    auto load_stage = [&](int stage, int k0) {
        const uint32_t s0 = sb + stage * GS_STAGE;
        #pragma unroll
        for (int it = 0; it < MT / 64; ++it) {
            const int idx = it * 256 + tid;
            const int row = idx >> 2;
            const int cc  = idx & 3;
            CPASYNC(s0 + tile_off(row, cc),
                    A + (size_t)(m0 + row) * Ktot + k0 + cc * 8);
        }
        #pragma unroll
        for (int it = 0; it < 2; ++it) {
            const int idx = it * 256 + tid;
            const int row = idx >> 4;
            const int cc  = idx & 15;
            const uint32_t so = boff(row, cc);
            const size_t gb = (size_t)(k0 + row) * Ntot + n0 + cc * 8;
            CPASYNC(s0 + GS_BH + so, Bh + gb);
            CPASYNC(s0 + GS_BL + so, Bl + gb);
        }
        CPCOMMIT();
    };

    const int nk = Ktot / 32;
    load_stage(0, 0);
    load_stage(1, 32);

    const int hilo_b = (lane >> 4) * (GS_BL - GS_BH);
    const int krow_b = lane & 15;

    int st = 0;
    for (int ki = 0; ki < nk; ++ki) {
        if (ki + 2 <= nk) { CPWAIT1(); } else { CPWAIT0(); }
        __syncthreads();
        if (ki + 2 < nk) {
            int st2 = st + 2; if (st2 >= 3) st2 -= 3;
            load_stage(st2, (ki + 2) * 32);
        }

        const uint32_t s0 = sb + st * GS_STAGE;
        #pragma unroll
        for (int ks = 0; ks < 2; ++ks) {
            uint32_t b4[4][4];
            #pragma unroll
            for (int ni = 0; ni < 4; ++ni) {
                const int chn = wn * 4 + ni;
                ldmatrix_x4_trans(b4[ni],
                    s0 + GS_BH + hilo_b + boff(ks * 16 + krow_b, chn));
            }
            #pragma unroll
            for (int mi = 0; mi < MI; ++mi) {
                uint32_t af[4];
                const int r = wm * (MT / 2) + mi * 16 + (lane & 15);
                ldmatrix_x4(af, s0 + tile_off(r, ks * 2 + (lane >> 4)));
                #pragma unroll
                for (int ni = 0; ni < 4; ++ni) mma_fp16(c[mi][ni], af, b4[ni] + 0);
                #pragma unroll
                for (int ni = 0; ni < 4; ++ni) mma_fp16(c[mi][ni], af, b4[ni] + 2);
            }
        }
        if (++st >= 3) st = 0;
    }

    #pragma unroll
    for (int mi = 0; mi < MI; ++mi) {
        #pragma unroll
        for (int ni = 0; ni < 4; ++ni) {
            const int r0  = m0 + wm * (MT / 2) + mi * 16 + (lane >> 2);
            const int col = n0 + wn * 32 + ni * 8 + (lane & 3) * 2;
            const float b0 = bias[col], b1 = bias[col + 1];
            #pragma unroll
            for (int half = 0; half < 2; ++half) {
                const int r = r0 + half * 8;
                float vx = c[mi][ni][half * 2 + 0] + b0;
                float vy = c[mi][ni][half * 2 + 1] + b1;
                if (QKV) {
                    const int bb  = r >> 10;
                    const int iq  = r & 1023;
                    const int sel = col / DIM;
                    const int nc  = col - sel * DIM;
                    const int h   = nc >> 6;
                    const int d   = nc & 63;
                    const size_t idx = (((size_t)(bb * HEADS + h)) * SEQ + iq) * HD + d;
                    if (sel == 0) {
                        *(uint32_t*)(g_q + idx) = h2pack(vx * QSCALE, vy * QSCALE);
                    } else if (sel == 1) {
                        *(uint32_t*)(g_k + idx) = h2pack(vx, vy);
                    } else {
                        *(uint32_t*)(g_v + idx) = h2pack(vx, vy);
                    }
                } else {
                    float2 v; v.x = vx; v.y = vy;
                    *(float2*)&Cout[(size_t)r * Ntot + col] = v;
                }
            }
        }
    }
}

// ---------------- flash attention, fp16 single-term (cp.async 2-stage K/V) ----------------
#define FQ  0
#define FKV 16384
#define FKV_STRIDE 16384
#define FV_O 8192
#define FLASH_SMEM (16384 + 2 * FKV_STRIDE)   // 49152

__global__ __launch_bounds__(256, 2)
void flash_mma()
{
    extern __shared__ char fs[];
    const uint32_t sb = smem_u32(fs);
    const int tid  = threadIdx.x;
    const int lane = tid & 31;
    const int wid  = tid >> 5;
    const int bh   = blockIdx.y;
    const int q0   = blockIdx.x * 128;
    const size_t base = (size_t)bh * SEQ * HD;

    auto load_kv = [&](int stage, int kb) {
        const uint32_t s0 = sb + FKV + stage * FKV_STRIDE;
        #pragma unroll
        for (int i = 0; i < 2; ++i) {
            const int idx = i * 256 + tid;
            const int row = idx >> 3, ch = idx & 7;
            const uint32_t so = foff(row, ch);
            const size_t g = base + (size_t)(kb + row) * HD + ch * 8;
            CPASYNC(s0 + so,        g_k + g);
            CPASYNC(s0 + FV_O + so, g_v + g);
        }
        CPCOMMIT();
    };

    load_kv(0, 0);
    #pragma unroll
    for (int i = 0; i < 4; ++i) {
        const int idx = i * 256 + tid;
        const int row = idx >> 3, ch = idx & 7;
        const uint32_t so = foff(row, ch);
        const size_t g = base + (size_t)(q0 + row) * HD + ch * 8;
        *(uint4*)(fs + FQ + so) = *(const uint4*)(g_q + g);
    }

    float O[8][4];
    #pragma unroll
    for (int i = 0; i < 8; ++i)
        #pragma unroll
        for (int t = 0; t < 4; ++t) O[i][t] = 0.f;
    float m0 = -1e30f, m1 = -1e30f, l0 = 0.f, l1 = 0.f;

    const int nkb = SEQ / 64;
    for (int kbi = 0; kbi < nkb; ++kbi) {
        CPWAIT0();
        __syncthreads();
        if (kbi + 1 < nkb) load_kv((kbi + 1) & 1, (kbi + 1) * 64);

        const uint32_t s0 = sb + FKV + (kbi & 1) * FKV_STRIDE;

        float c[8][4];
        #pragma unroll
        for (int i = 0; i < 8; ++i)
            #pragma unroll
            for (int t = 0; t < 4; ++t) c[i][t] = 0.f;

        #pragma unroll
        for (int ks = 0; ks < 4; ++ks) {
            uint32_t qf[4];
            {
                const int r  = wid * 16 + (lane & 15);
                const int ch = ks * 2 + (lane >> 4);
                ldmatrix_x4(qf, sb + FQ + foff(r, ch));
            }
            #pragma unroll
            for (int jj = 0; jj < 4; ++jj) {
                uint32_t kb4[4];
                const int row = (2 * jj + (lane >> 4)) * 8 + (lane & 7);
                const int ch  = ks * 2 + ((lane >> 3) & 1);
                ldmatrix_x4(kb4, s0 + foff(row, ch));
                mma_fp16(c[2*jj + 0], qf, kb4 + 0);
                mma_fp16(c[2*jj + 1], qf, kb4 + 2);
            }
        }

        // online softmax (log2 domain)
        float rm0 = -1e30f, rm1 = -1e30f;
        #pragma unroll
        for (int ni = 0; ni < 8; ++ni) {
            rm0 = fmaxf(rm0, fmaxf(c[ni][0], c[ni][1]));
            rm1 = fmaxf(rm1, fmaxf(c[ni][2], c[ni][3]));
        }
        #pragma unroll
        for (int off = 1; off < 4; off <<= 1) {
            rm0 = fmaxf(rm0, __shfl_xor_sync(0xffffffffu, rm0, off));
            rm1 = fmaxf(rm1, __shfl_xor_sync(0xffffffffu, rm1, off));
        }
        const float mn0 = fmaxf(m0, rm0), mn1 = fmaxf(m1, rm1);
        if (!__all_sync(0xffffffffu, (mn0 == m0) && (mn1 == m1))) {
            const float cor0 = ex2(m0 - mn0), cor1 = ex2(m1 - mn1);
            l0 *= cor0; l1 *= cor1;
            #pragma unroll
            for (int nd = 0; nd < 8; ++nd) {
                O[nd][0] *= cor0; O[nd][1] *= cor0;
                O[nd][2] *= cor1; O[nd][3] *= cor1;
            }
            m0 = mn0; m1 = mn1;
        }

        float rs0 = 0.f, rs1 = 0.f;
        #pragma unroll
        for (int ni = 0; ni < 8; ++ni) {
            c[ni][0] = ex2(c[ni][0] - m0);
            c[ni][1] = ex2(c[ni][1] - m0);
            c[ni][2] = ex2(c[ni][2] - m1);
            c[ni][3] = ex2(c[ni][3] - m1);
            rs0 += c[ni][0] + c[ni][1];
            rs1 += c[ni][2] + c[ni][3];
        }
        #pragma unroll
        for (int off = 1; off < 4; off <<= 1) {
            rs0 += __shfl_xor_sync(0xffffffffu, rs0, off);
            rs1 += __shfl_xor_sync(0xffffffffu, rs1, off);
        }
        l0 += rs0;
        l1 += rs1;

        #pragma unroll
        for (int ks2 = 0; ks2 < 4; ++ks2) {
            uint32_t pf[4];
            pf[0] = h2pack(c[2*ks2][0],   c[2*ks2][1]);
            pf[1] = h2pack(c[2*ks2][2],   c[2*ks2][3]);
            pf[2] = h2pack(c[2*ks2+1][0], c[2*ks2+1][1]);
            pf[3] = h2pack(c[2*ks2+1][2], c[2*ks2+1][3]);
            #pragma unroll
            for (int jj = 0; jj < 4; ++jj) {
                uint32_t vb4[4];
                const int row = ks2 * 16 + (lane & 15);
                const int ch  = 2 * jj + (lane >> 4);
                ldmatrix_x4_trans(vb4, s0 + FV_O + foff(row, ch));
                mma_fp16(O[2*jj + 0], pf, vb4 + 0);
                mma_fp16(O[2*jj + 1], pf, vb4 + 2);
            }
        }
    }

    // epilogue: fp16 single attention out
    const float inv0 = 1.f / l0, inv1 = 1.f / l1;
    const int b = bh / HEADS;
    const int h = bh - b * HEADS;
    const int r0 = q0 + wid * 16 + (lane >> 2);
    #pragma unroll
    for (int nd = 0; nd < 8; ++nd) {
        const int col = h * HD + nd * 8 + (lane & 3) * 2;
        size_t idx = ((size_t)(b * SEQ + r0)) * DIM + col;
        *(uint32_t*)(g_a + idx) = h2pack(O[nd][0] * inv0, O[nd][1] * inv0);
        idx = ((size_t)(b * SEQ + r0 + 8)) * DIM + col;
        *(uint32_t*)(g_a + idx) = h2pack(O[nd][2] * inv1, O[nd][3] * inv1);
    }
}

// ---------------- launch ----------------
extern "C" void kernel_launch(void* const* d_in, const int* in_sizes, int n_in,
                              void* d_out, int out_size)
{
    const float* x     = (const float*)d_in[0];
    const float* w_qkv = (const float*)d_in[1];
    const float* b_qkv = (const float*)d_in[2];
    const float* w_out = (const float*)d_in[3];
    const float* b_out = (const float*)d_in[4];
    float* out = (float*)d_out;

    __half *xp, *wqh, *wql, *woh, *wol, *ap;
    cudaGetSymbolAddress((void**)&xp,  g_x);
    cudaGetSymbolAddress((void**)&wqh, g_wqh);
    cudaGetSymbolAddress((void**)&wql, g_wql);
    cudaGetSymbolAddress((void**)&woh, g_woh);
    cudaGetSymbolAddress((void**)&wol, g_wol);
    cudaGetSymbolAddress((void**)&ap,  g_a);

    cudaFuncSetAttribute((const void*)gemm_mma<true, 128>,
                         cudaFuncAttributeMaxDynamicSharedMemorySize, GEMM_SMEM);
    cudaFuncSetAttribute((const void*)gemm_mma<false, 64>,
                         cudaFuncAttributeMaxDynamicSharedMemorySize, GEMM_SMEM);
    cudaFuncSetAttribute(flash_mma, cudaFuncAttributeMaxDynamicSharedMemorySize, FLASH_SMEM);

    // 0) fp32 -> fp16 conversions (x single; weights hi/lo), one launch
    split_all<<<(NSPLIT4 + 255) / 256, 256>>>(x, w_qkv, w_out);

    // 1) QKV GEMM (fp16 2-term, 128M tiles) -> q/k/v fp16
    gemm_mma<true, 128><<<dim3(QKV_N / 128, M_TOT / 128), 256, GEMM_SMEM>>>(
        xp, wqh, wql, b_qkv, nullptr, QKV_N, DIM);

    // 2) flash attention (fp16 single-term) -> g_a fp16
    flash_mma<<<dim3(SEQ / 128, B_SZ * HEADS), 256, FLASH_SMEM>>>();

    // 3) out projection (fp16 2-term, 64M tiles) -> d_out
    gemm_mma<false, 64><<<dim3(DIM / 128, M_TOT / 64), 256, GEMM_SMEM>>>(
        ap, woh, wol, b_out, out, DIM, DIM);
}